// round 10
// baseline (speedup 1.0000x reference)
#include <cuda_runtime.h>
#include <cuda_bf16.h>
#include <math.h>
#include <stdint.h>

// ---------------- constants ----------------
#define NTOK     2048
#define HIDDEN   2880
#define HEAD_DIM 64
#define N_HEADS  64
#define N_KV     8
#define Q_MULT   8
#define QKV_DIM  5120      // 64*(64+16)
#define Q_DIM    4096      // 64*64
#define KV_OFF   4096
#define V_OFF    4608
#define WINDOW   128

// ---------------- scratch (no cudaMalloc allowed) ----------------
__device__ float g_QKV[NTOK * QKV_DIM];
__device__ __nv_bfloat16 g_Ahi[NTOK * Q_DIM];        // GEMM A operand, split hi
__device__ __nv_bfloat16 g_Alo[NTOK * Q_DIM];
__device__ __nv_bfloat16 g_B1hi[QKV_DIM * HIDDEN];   // qkv_w split+transposed
__device__ __nv_bfloat16 g_B1lo[QKV_DIM * HIDDEN];
__device__ __nv_bfloat16 g_B2hi[HIDDEN * Q_DIM];     // out_w split+transposed
__device__ __nv_bfloat16 g_B2lo[HIDDEN * Q_DIM];

// ---------------- helpers ----------------
__device__ __forceinline__ uint32_t smem_u32(const void* p) {
    uint32_t a;
    asm("{ .reg .u64 t; cvta.to.shared.u64 t, %1; cvt.u32.u64 %0, t; }" : "=r"(a) : "l"(p));
    return a;
}
__device__ __forceinline__ void cp16(uint32_t dst, const void* src) {
    asm volatile("cp.async.cg.shared.global [%0], [%1], 16;" :: "r"(dst), "l"(src));
}
#define CP_COMMIT() asm volatile("cp.async.commit_group;" ::: "memory")
#define CP_WAIT(n)  asm volatile("cp.async.wait_group %0;" :: "n"(n) : "memory")

__device__ __forceinline__ void ldsm_x4(uint32_t* r, uint32_t addr) {
    asm volatile("ldmatrix.sync.aligned.m8n8.x4.shared.b16 {%0,%1,%2,%3}, [%4];"
                 : "=r"(r[0]), "=r"(r[1]), "=r"(r[2]), "=r"(r[3]) : "r"(addr));
}
__device__ __forceinline__ void mma16816(float* c, const uint32_t* a, uint32_t b0, uint32_t b1) {
    asm volatile(
        "mma.sync.aligned.m16n8k16.row.col.f32.bf16.bf16.f32 "
        "{%0,%1,%2,%3}, {%4,%5,%6,%7}, {%8,%9}, {%0,%1,%2,%3};"
        : "+f"(c[0]), "+f"(c[1]), "+f"(c[2]), "+f"(c[3])
        : "r"(a[0]), "r"(a[1]), "r"(a[2]), "r"(a[3]), "r"(b0), "r"(b1));
}
__device__ __forceinline__ void split_bf16(float v, __nv_bfloat16& h, __nv_bfloat16& l) {
    h = __float2bfloat16(v);
    l = __float2bfloat16(v - __bfloat162float(h));
}
__device__ __forceinline__ uint32_t pack2(__nv_bfloat16 a, __nv_bfloat16 b) {
    __nv_bfloat162 t = __halves2bfloat162(a, b);
    return *(uint32_t*)&t;
}
__device__ __forceinline__ uint32_t pack_split(float a, float b, uint32_t* lo) {
    __nv_bfloat16 ha, la, hb, lb;
    split_bf16(a, ha, la);
    split_bf16(b, hb, lb);
    *lo = pack2(la, lb);
    return pack2(ha, hb);
}

// ---------------- RMSNorm fused with A-split ----------------
__global__ void rmsnorm_split_kernel(const float* __restrict__ x,
                                     const float* __restrict__ w,
                                     __nv_bfloat16* __restrict__ hi,
                                     __nv_bfloat16* __restrict__ lo) {
    int row = blockIdx.x;
    const float4* xr = (const float4*)(x + row * HIDDEN);
    const float4* wr = (const float4*)w;

    float s = 0.f;
    for (int i = threadIdx.x; i < HIDDEN / 4; i += 256) {
        float4 v = xr[i];
        s += v.x * v.x + v.y * v.y + v.z * v.z + v.w * v.w;
    }
    __shared__ float red[256];
    red[threadIdx.x] = s;
    __syncthreads();
    for (int off = 128; off > 0; off >>= 1) {
        if (threadIdx.x < off) red[threadIdx.x] += red[threadIdx.x + off];
        __syncthreads();
    }
    float r = rsqrtf(red[0] / (float)HIDDEN + 1e-5f);

    for (int i = threadIdx.x; i < HIDDEN / 4; i += 256) {
        float4 v = xr[i], ww = wr[i];
        float t0 = v.x * r * ww.x, t1 = v.y * r * ww.y;
        float t2 = v.z * r * ww.z, t3 = v.w * r * ww.w;
        __nv_bfloat16 h0, h1, h2, h3, l0, l1, l2, l3;
        split_bf16(t0, h0, l0); split_bf16(t1, h1, l1);
        split_bf16(t2, h2, l2); split_bf16(t3, h3, l3);
        uint2 hp, lp;
        hp.x = pack2(h0, h1); hp.y = pack2(h2, h3);
        lp.x = pack2(l0, l1); lp.y = pack2(l2, l3);
        ((uint2*)(hi + (size_t)row * HIDDEN))[i] = hp;
        ((uint2*)(lo + (size_t)row * HIDDEN))[i] = lp;
    }
}

// ---------------- split + transpose: in[K][N] fp32 -> out[N][K] bf16 hi/lo ----------------
__global__ void split_transpose_kernel(const float* __restrict__ in,
                                       __nv_bfloat16* __restrict__ hi,
                                       __nv_bfloat16* __restrict__ lo,
                                       int K, int N) {
    __shared__ float t[32][33];
    int k0 = blockIdx.y * 32, n0 = blockIdx.x * 32;
    int tx = threadIdx.x, ty = threadIdx.y;  // 32 x 8
#pragma unroll
    for (int i = 0; i < 4; i++)
        t[ty + 8 * i][tx] = in[(size_t)(k0 + ty + 8 * i) * N + n0 + tx];
    __syncthreads();
#pragma unroll
    for (int i = 0; i < 4; i++) {
        float v = t[tx][ty + 8 * i];
        __nv_bfloat16 h, l;
        split_bf16(v, h, l);
        size_t idx = (size_t)(n0 + ty + 8 * i) * K + k0 + tx;
        hi[idx] = h;
        lo[idx] = l;
    }
}

// ---------------- mma.sync split-bf16 GEMM ----------------
// K chunk 64, 2-stage cp.async (144KB smem), 8 warps (2x4), warp tile 64x32.
// smem row = 72 bf16 (144B = 9x16B, odd -> conflict-free ldsm).
#define TROW      72                       // padded row (bf16) for chunk 64
#define ARR_BYTES (128 * TROW * 2)         // 18432
#define STG_BYTES (4 * ARR_BYTES)          // 73728
#define OFF_AHI   0
#define OFF_ALO   ARR_BYTES
#define OFF_BHI   (2 * ARR_BYTES)
#define OFF_BLO   (3 * ARR_BYTES)
#define GEMM_SMEM (2 * STG_BYTES)          // 147456

template <bool RESID>
__global__ void __launch_bounds__(256, 1) gemm_mma(
    const __nv_bfloat16* __restrict__ Ahi, const __nv_bfloat16* __restrict__ Alo,
    const __nv_bfloat16* __restrict__ Bhi, const __nv_bfloat16* __restrict__ Blo,
    const float* __restrict__ R, float* __restrict__ C, int N, int K) {
    extern __shared__ char smem[];
    const uint32_t sb = smem_u32(smem);
    const int tid  = threadIdx.x;
    const int warp = tid >> 5;
    const int lane = tid & 31;
    const int row0 = blockIdx.y * 128;
    const int col0 = blockIdx.x * 128;

    // loader: each thread covers one row, one 32-elem k-half (4 x 16B)
    const int lrow = tid >> 1;
    const int lkh  = (tid & 1) * 32;

    const __nv_bfloat16* pAhi = Ahi + (size_t)(row0 + lrow) * K + lkh;
    const __nv_bfloat16* pAlo = Alo + (size_t)(row0 + lrow) * K + lkh;
    int brow = (col0 + lrow < N) ? (col0 + lrow) : 0;
    const __nv_bfloat16* pBhi = Bhi + (size_t)brow * K + lkh;
    const __nv_bfloat16* pBlo = Blo + (size_t)brow * K + lkh;

    const uint32_t sdst = sb + (uint32_t)lrow * (TROW * 2) + (uint32_t)lkh * 2;

    const int wm0 = (warp >> 2) * 64;
    const int wn0 = (warp & 3) * 32;

    const uint32_t afo = (uint32_t)(wm0 + (lane & 15)) * (TROW * 2) + ((lane >> 4) << 4);
    const uint32_t bfo = (uint32_t)(wn0 + (lane & 15)) * (TROW * 2) + ((lane >> 4) << 4);

    float acc[4][4][4];
#pragma unroll
    for (int i = 0; i < 4; i++)
#pragma unroll
        for (int j = 0; j < 4; j++)
#pragma unroll
            for (int k = 0; k < 4; k++) acc[i][j][k] = 0.f;

    const int nc = K >> 6;   // chunk 64

    {
#pragma unroll
        for (int u = 0; u < 4; u++) {
            cp16(sdst + OFF_AHI + u * 16, pAhi + u * 8);
            cp16(sdst + OFF_ALO + u * 16, pAlo + u * 8);
            cp16(sdst + OFF_BHI + u * 16, pBhi + u * 8);
            cp16(sdst + OFF_BLO + u * 16, pBlo + u * 8);
        }
        CP_COMMIT();
    }

    for (int c = 0; c < nc; c++) {
        const uint32_t cur = (uint32_t)(c & 1) * STG_BYTES;
        if (c + 1 < nc) {
            const uint32_t nxt = (uint32_t)((c + 1) & 1) * STG_BYTES;
            const int ke = (c + 1) * 64;
#pragma unroll
            for (int u = 0; u < 4; u++) {
                cp16(sdst + nxt + OFF_AHI + u * 16, pAhi + ke + u * 8);
                cp16(sdst + nxt + OFF_ALO + u * 16, pAlo + ke + u * 8);
                cp16(sdst + nxt + OFF_BHI + u * 16, pBhi + ke + u * 8);
                cp16(sdst + nxt + OFF_BLO + u * 16, pBlo + ke + u * 8);
            }
            CP_COMMIT();
            CP_WAIT(1);
        } else {
            CP_WAIT(0);
        }
        __syncthreads();

#pragma unroll
        for (int ks = 0; ks < 4; ks++) {          // 4 k16 steps per chunk 64
            const uint32_t ko = (uint32_t)ks * 32;
            uint32_t ah[4][4], al[4][4];
#pragma unroll
            for (int mt = 0; mt < 4; mt++) {
                ldsm_x4(ah[mt], sb + cur + OFF_AHI + afo + mt * (16 * TROW * 2) + ko);
                ldsm_x4(al[mt], sb + cur + OFF_ALO + afo + mt * (16 * TROW * 2) + ko);
            }
#pragma unroll
            for (int np = 0; np < 2; np++) {
                uint32_t bh[4], bl[4];
                const uint32_t bo = bfo + np * (16 * TROW * 2) + ko;
                ldsm_x4(bh, sb + cur + OFF_BHI + bo);
                ldsm_x4(bl, sb + cur + OFF_BLO + bo);
#pragma unroll
                for (int mt = 0; mt < 4; mt++) {
#pragma unroll
                    for (int h2 = 0; h2 < 2; h2++) {
                        const int nt = np * 2 + h2;
                        mma16816(acc[mt][nt], ah[mt], bh[h2], bh[h2 + 2]);
                        mma16816(acc[mt][nt], ah[mt], bl[h2], bl[h2 + 2]);
                        mma16816(acc[mt][nt], al[mt], bh[h2], bh[h2 + 2]);
                    }
                }
            }
        }
        __syncthreads();
    }

    const int g = lane >> 2, cq = lane & 3;
#pragma unroll
    for (int mt = 0; mt < 4; mt++) {
#pragma unroll
        for (int nt = 0; nt < 4; nt++) {
            const int col = col0 + wn0 + nt * 8 + cq * 2;
            if (col < N) {
                const int m0 = row0 + wm0 + mt * 16 + g;
                float2 v0 = make_float2(acc[mt][nt][0], acc[mt][nt][1]);
                float2 v1 = make_float2(acc[mt][nt][2], acc[mt][nt][3]);
                if (RESID) {
                    float2 r0 = *(const float2*)(R + (size_t)m0 * N + col);
                    float2 r1 = *(const float2*)(R + (size_t)(m0 + 8) * N + col);
                    v0.x += r0.x; v0.y += r0.y; v1.x += r1.x; v1.y += r1.y;
                }
                *(float2*)(C + (size_t)m0 * N + col) = v0;
                *(float2*)(C + (size_t)(m0 + 8) * N + col) = v1;
            }
        }
    }
}

// ---------------- RoPE (YaRN/NTK) in place on Q and K ----------------
__global__ void rope_kernel(float* __restrict__ qkv) {
    int i = blockIdx.x;
    __shared__ float s_cos[32], s_sin[32];
    int tid = threadIdx.x;
    if (tid < 32) {
        float d   = (float)tid;
        float lnB = logf(150000.0f);
        float freq = expf(lnB * d / 32.0f);
        float low  = 32.0f * logf(4096.0f / (32.0f * 6.2831853071795864f)) / lnB;
        float high = 32.0f * logf(4096.0f / (6.2831853071795864f)) / lnB;
        float interp = 1.0f / (32.0f * freq);
        float extrap = 1.0f / freq;
        float ramp = (d - low) / (high - low);
        float mask = 1.0f - fminf(fmaxf(ramp, 0.0f), 1.0f);
        float inv  = interp * (1.0f - mask) + extrap * mask;
        float conc = 0.1f * logf(32.0f) + 1.0f;
        float ang  = (float)i * inv;
        s_cos[tid] = cosf(ang) * conc;
        s_sin[tid] = sinf(ang) * conc;
    }
    __syncthreads();
    float* base = qkv + (size_t)i * QKV_DIM;
    for (int idx = tid; idx < 72 * 32; idx += blockDim.x) {
        int head = idx >> 5;
        int d    = idx & 31;
        float* p = (head < 64) ? (base + head * 64)
                               : (base + KV_OFF + (head - 64) * 64);
        float x1 = p[d], x2 = p[d + 32];
        float c = s_cos[d], s = s_sin[d];
        p[d]      = x1 * c - x2 * s;
        p[d + 32] = x2 * c + x1 * s;
    }
}

// ---------------- MMA sliding-window attention with sink (verified R8) ----------------
#define NC        160
#define SRQ       144
#define SRVT      336
#define AOFF_QHI  0
#define AOFF_QLO  9216
#define AOFF_KHI  18432
#define AOFF_KLO  41472
#define AOFF_VHI  64512
#define AOFF_VLO  86016
#define AOFF_O    107520
#define AOFF_SM   124928
#define AOFF_SS   125440
#define AOFF_DEN  125952
#define ATTN_SMEM 126208

__global__ void __launch_bounds__(256, 1) attn_mma_kernel(
    const float* __restrict__ qkv, const float* __restrict__ sinks,
    __nv_bfloat16* __restrict__ ohi, __nv_bfloat16* __restrict__ olo) {
    extern __shared__ char smem[];
    const uint32_t sb = smem_u32(smem);
    const int tid  = threadIdx.x;
    const int warp = tid >> 5;
    const int lane = tid & 31;
    const int t0   = blockIdx.x * 8;
    const int kv   = blockIdx.y;
    const int j0   = (t0 >= 128) ? (t0 - 127) : 0;
    const int jmax = t0 + 7;
    const float NEGINF = __int_as_float(0xff800000);

    if (tid < 128) {
        int r = tid >> 1, hf = tid & 1;
        int i = t0 + (r & 7);
        int h = kv * 8 + (r >> 3);
        const float4* src = (const float4*)(qkv + (size_t)i * QKV_DIM + h * 64 + hf * 32);
        char* dh = smem + AOFF_QHI + r * SRQ + hf * 64;
        char* dl = smem + AOFF_QLO + r * SRQ + hf * 64;
#pragma unroll
        for (int u = 0; u < 8; u++) {
            float4 v = src[u];
            __nv_bfloat16 h0, h1, h2, h3, l0, l1, l2, l3;
            split_bf16(v.x * 0.125f, h0, l0); split_bf16(v.y * 0.125f, h1, l1);
            split_bf16(v.z * 0.125f, h2, l2); split_bf16(v.w * 0.125f, h3, l3);
            *(uint2*)(dh + u * 8) = make_uint2(pack2(h0, h1), pack2(h2, h3));
            *(uint2*)(dl + u * 8) = make_uint2(pack2(l0, l1), pack2(l2, l3));
        }
    }
    for (int idx = tid; idx < NC * 2; idx += 256) {
        int c = idx >> 1, hf = idx & 1;
        int j = j0 + c;
        bool ok = (j <= jmax);
        const float4* src = (const float4*)(qkv + (size_t)j * QKV_DIM + KV_OFF + kv * 64 + hf * 32);
        char* dh = smem + AOFF_KHI + c * SRQ + hf * 64;
        char* dl = smem + AOFF_KLO + c * SRQ + hf * 64;
#pragma unroll
        for (int u = 0; u < 8; u++) {
            float4 v = make_float4(0.f, 0.f, 0.f, 0.f);
            if (ok) v = src[u];
            __nv_bfloat16 h0, h1, h2, h3, l0, l1, l2, l3;
            split_bf16(v.x, h0, l0); split_bf16(v.y, h1, l1);
            split_bf16(v.z, h2, l2); split_bf16(v.w, h3, l3);
            *(uint2*)(dh + u * 8) = make_uint2(pack2(h0, h1), pack2(h2, h3));
            *(uint2*)(dl + u * 8) = make_uint2(pack2(l0, l1), pack2(l2, l3));
        }
    }
    if (tid < 80) {
        int p = tid;
        int ja = j0 + 2 * p, jb = ja + 1;
        bool oka = (ja <= jmax), okb = (jb <= jmax);
        const float4* sa = (const float4*)(qkv + (size_t)ja * QKV_DIM + V_OFF + kv * 64);
        const float4* sv = (const float4*)(qkv + (size_t)jb * QKV_DIM + V_OFF + kv * 64);
#pragma unroll
        for (int d4 = 0; d4 < 16; d4++) {
            float4 va = make_float4(0.f, 0.f, 0.f, 0.f);
            float4 vb = make_float4(0.f, 0.f, 0.f, 0.f);
            if (oka) va = sa[d4];
            if (okb) vb = sv[d4];
            float fa[4] = {va.x, va.y, va.z, va.w};
            float fb[4] = {vb.x, vb.y, vb.z, vb.w};
#pragma unroll
            for (int e = 0; e < 4; e++) {
                int d = d4 * 4 + e;
                __nv_bfloat16 ha, la, hb, lb;
                split_bf16(fa[e], ha, la);
                split_bf16(fb[e], hb, lb);
                *(uint32_t*)(smem + AOFF_VHI + d * SRVT + p * 4) = pack2(ha, hb);
                *(uint32_t*)(smem + AOFF_VLO + d * SRVT + p * 4) = pack2(la, lb);
            }
        }
    }
    __syncthreads();

    const int wm = warp >> 1, wn = warp & 1;
    const int wm0 = wm * 16;
    const int g = lane >> 2, q = lane & 3;

    float acc[10][4];
#pragma unroll
    for (int nt = 0; nt < 10; nt++)
#pragma unroll
        for (int e = 0; e < 4; e++) acc[nt][e] = 0.f;

    const uint32_t aoff = (uint32_t)(wm0 + (lane & 15)) * SRQ + ((lane >> 4) << 4);
#pragma unroll
    for (int kc = 0; kc < 4; kc++) {
        uint32_t qh[4], ql[4];
        ldsm_x4(qh, sb + AOFF_QHI + aoff + kc * 32);
        ldsm_x4(ql, sb + AOFF_QLO + aoff + kc * 32);
#pragma unroll
        for (int np = 0; np < 5; np++) {
            uint32_t bh[4], bl[4];
            uint32_t boff = (uint32_t)(wn * 80 + np * 16 + (lane & 15)) * SRQ
                          + ((lane >> 4) << 4) + kc * 32;
            ldsm_x4(bh, sb + AOFF_KHI + boff);
            ldsm_x4(bl, sb + AOFF_KLO + boff);
#pragma unroll
            for (int h2 = 0; h2 < 2; h2++) {
                const int nt = np * 2 + h2;
                mma16816(acc[nt], qh, bh[h2], bh[h2 + 2]);
                mma16816(acc[nt], qh, bl[h2], bl[h2 + 2]);
                mma16816(acc[nt], ql, bh[h2], bh[h2 + 2]);
            }
        }
    }

    const int lo_c = (t0 >= 128) ? g : 0;
    const int hi_c = (t0 >= 128) ? (127 + g) : (t0 + g);
    bool val0[10], val1[10];
    float vmax0 = NEGINF, vmax1 = NEGINF;
#pragma unroll
    for (int nt = 0; nt < 10; nt++) {
        int c0 = wn * 80 + nt * 8 + q * 2;
        int c1 = c0 + 1;
        val0[nt] = (c0 >= lo_c) && (c0 <= hi_c);
        val1[nt] = (c1 >= lo_c) && (c1 <= hi_c);
        if (val0[nt]) { vmax0 = fmaxf(vmax0, acc[nt][0]); vmax1 = fmaxf(vmax1, acc[nt][2]); }
        if (val1[nt]) { vmax0 = fmaxf(vmax0, acc[nt][1]); vmax1 = fmaxf(vmax1, acc[nt][3]); }
    }
    vmax0 = fmaxf(vmax0, __shfl_xor_sync(0xffffffffu, vmax0, 1));
    vmax0 = fmaxf(vmax0, __shfl_xor_sync(0xffffffffu, vmax0, 2));
    vmax1 = fmaxf(vmax1, __shfl_xor_sync(0xffffffffu, vmax1, 1));
    vmax1 = fmaxf(vmax1, __shfl_xor_sync(0xffffffffu, vmax1, 2));
    float* sM = (float*)(smem + AOFF_SM);
    if (q == 0) { sM[wn * 64 + wm0 + g] = vmax0; sM[wn * 64 + wm0 + g + 8] = vmax1; }
    __syncthreads();

    const float snk0 = sinks[kv * 8 + 2 * wm];
    const float snk1 = sinks[kv * 8 + 2 * wm + 1];
    const float m0 = fmaxf(fmaxf(sM[wm0 + g], sM[64 + wm0 + g]), snk0);
    const float m1 = fmaxf(fmaxf(sM[wm0 + g + 8], sM[64 + wm0 + g + 8]), snk1);
    float sum0 = 0.f, sum1 = 0.f;
#pragma unroll
    for (int nt = 0; nt < 10; nt++) {
        acc[nt][0] = val0[nt] ? __expf(acc[nt][0] - m0) : 0.f;
        acc[nt][1] = val1[nt] ? __expf(acc[nt][1] - m0) : 0.f;
        acc[nt][2] = val0[nt] ? __expf(acc[nt][2] - m1) : 0.f;
        acc[nt][3] = val1[nt] ? __expf(acc[nt][3] - m1) : 0.f;
        sum0 += acc[nt][0] + acc[nt][1];
        sum1 += acc[nt][2] + acc[nt][3];
    }
    sum0 += __shfl_xor_sync(0xffffffffu, sum0, 1);
    sum0 += __shfl_xor_sync(0xffffffffu, sum0, 2);
    sum1 += __shfl_xor_sync(0xffffffffu, sum1, 1);
    sum1 += __shfl_xor_sync(0xffffffffu, sum1, 2);
    float* sS = (float*)(smem + AOFF_SS);
    if (q == 0) { sS[wn * 64 + wm0 + g] = sum0; sS[wn * 64 + wm0 + g + 8] = sum1; }
    __syncthreads();

    float* sDen = (float*)(smem + AOFF_DEN);
    if (wn == 0 && q == 0) {
        int r0 = wm0 + g, r1 = r0 + 8;
        sDen[r0] = 1.f / (sS[r0] + sS[64 + r0] + __expf(snk0 - m0));
        sDen[r1] = 1.f / (sS[r1] + sS[64 + r1] + __expf(snk1 - m1));
    }

    float accO[8][4];
#pragma unroll
    for (int nt = 0; nt < 8; nt++)
#pragma unroll
        for (int e = 0; e < 4; e++) accO[nt][e] = 0.f;

#pragma unroll
    for (int kc = 0; kc < 5; kc++) {
        uint32_t ah[4], al[4];
        ah[0] = pack_split(acc[2 * kc][0],     acc[2 * kc][1],     &al[0]);
        ah[1] = pack_split(acc[2 * kc][2],     acc[2 * kc][3],     &al[1]);
        ah[2] = pack_split(acc[2 * kc + 1][0], acc[2 * kc + 1][1], &al[2]);
        ah[3] = pack_split(acc[2 * kc + 1][2], acc[2 * kc + 1][3], &al[3]);
#pragma unroll
        for (int np = 0; np < 4; np++) {
            uint32_t bh[4], bl[4];
            uint32_t boff = (uint32_t)(np * 16 + (lane & 15)) * SRVT
                          + ((lane >> 4) << 4) + wn * 160 + kc * 32;
            ldsm_x4(bh, sb + AOFF_VHI + boff);
            ldsm_x4(bl, sb + AOFF_VLO + boff);
#pragma unroll
            for (int h2 = 0; h2 < 2; h2++) {
                const int nt = np * 2 + h2;
                mma16816(accO[nt], ah, bh[h2], bh[h2 + 2]);
                mma16816(accO[nt], ah, bl[h2], bl[h2 + 2]);
                mma16816(accO[nt], al, bh[h2], bh[h2 + 2]);
            }
        }
    }

    float* sO = (float*)(smem + AOFF_O);
    if (wn == 0) {
#pragma unroll
        for (int nt = 0; nt < 8; nt++) {
            int c = nt * 8 + q * 2;
            *(float2*)&sO[(wm0 + g) * 68 + c]     = make_float2(accO[nt][0], accO[nt][1]);
            *(float2*)&sO[(wm0 + g + 8) * 68 + c] = make_float2(accO[nt][2], accO[nt][3]);
        }
    }
    __syncthreads();
    if (wn == 1) {
#pragma unroll
        for (int nt = 0; nt < 8; nt++) {
            int c = nt * 8 + q * 2;
            float2 a = *(float2*)&sO[(wm0 + g) * 68 + c];
            a.x += accO[nt][0]; a.y += accO[nt][1];
            *(float2*)&sO[(wm0 + g) * 68 + c] = a;
            float2 b = *(float2*)&sO[(wm0 + g + 8) * 68 + c];
            b.x += accO[nt][2]; b.y += accO[nt][3];
            *(float2*)&sO[(wm0 + g + 8) * 68 + c] = b;
        }
    }
    __syncthreads();

    for (int idx = tid; idx < 4096; idx += 256) {
        int r = idx >> 6, d = idx & 63;
        float v = sO[r * 68 + d] * sDen[r];
        int i = t0 + (r & 7);
        int col = kv * 512 + (r >> 3) * 64 + d;
        __nv_bfloat16 h, l;
        split_bf16(v, h, l);
        ohi[(size_t)i * Q_DIM + col] = h;
        olo[(size_t)i * Q_DIM + col] = l;
    }
}

// ---------------- launch ----------------
extern "C" void kernel_launch(void* const* d_in, const int* in_sizes, int n_in,
                              void* d_out, int out_size) {
    const float* x      = (const float*)d_in[0];
    const float* norm_w = (const float*)d_in[1];
    const float* qkv_w  = (const float*)d_in[2];
    const float* out_w  = (const float*)d_in[3];
    const float* sinks  = (const float*)d_in[4];
    float* out = (float*)d_out;

    float* QKV;
    __nv_bfloat16 *Ahi, *Alo, *B1hi, *B1lo, *B2hi, *B2lo;
    cudaGetSymbolAddress((void**)&QKV,  g_QKV);
    cudaGetSymbolAddress((void**)&Ahi,  g_Ahi);
    cudaGetSymbolAddress((void**)&Alo,  g_Alo);
    cudaGetSymbolAddress((void**)&B1hi, g_B1hi);
    cudaGetSymbolAddress((void**)&B1lo, g_B1lo);
    cudaGetSymbolAddress((void**)&B2hi, g_B2hi);
    cudaGetSymbolAddress((void**)&B2lo, g_B2lo);

    cudaFuncSetAttribute(gemm_mma<false>, cudaFuncAttributeMaxDynamicSharedMemorySize, GEMM_SMEM);
    cudaFuncSetAttribute(gemm_mma<true>,  cudaFuncAttributeMaxDynamicSharedMemorySize, GEMM_SMEM);
    cudaFuncSetAttribute(attn_mma_kernel, cudaFuncAttributeMaxDynamicSharedMemorySize, ATTN_SMEM);

    // 1. RMSNorm fused with A-split
    rmsnorm_split_kernel<<<NTOK, 256>>>(x, norm_w, Ahi, Alo);

    // 2. split+transpose qkv_w [2880][5120] -> B1 [5120][2880]
    {
        dim3 grid(QKV_DIM / 32, HIDDEN / 32);
        split_transpose_kernel<<<grid, dim3(32, 8)>>>(qkv_w, B1hi, B1lo, HIDDEN, QKV_DIM);
    }

    // 3. split+transpose out_w [4096][2880] -> B2 [2880][4096]
    {
        dim3 grid(HIDDEN / 32, Q_DIM / 32);
        split_transpose_kernel<<<grid, dim3(32, 8)>>>(out_w, B2hi, B2lo, Q_DIM, HIDDEN);
    }

    // 4. QKV GEMM (launch #4 -> ncu profiles this one)
    {
        dim3 grid(QKV_DIM / 128, NTOK / 128);
        gemm_mma<false><<<grid, 256, GEMM_SMEM>>>(Ahi, Alo, B1hi, B1lo, nullptr, QKV,
                                                  QKV_DIM, HIDDEN);
    }

    // 5. RoPE
    rope_kernel<<<NTOK, 256>>>(QKV);

    // 6. MMA attention (writes split bf16 A for GEMM2 directly)
    {
        dim3 grid(NTOK / 8, N_KV);
        attn_mma_kernel<<<grid, 256, ATTN_SMEM>>>(QKV, sinks, Ahi, Alo);
    }

    // 7. out projection + residual
    {
        dim3 grid((HIDDEN + 127) / 128, NTOK / 128);
        gemm_mma<true><<<grid, 256, GEMM_SMEM>>>(Ahi, Alo, B2hi, B2lo, x, out,
                                                 HIDDEN, Q_DIM);
    }
}

// round 11
// speedup vs baseline: 1.2595x; 1.2595x over previous
#include <cuda_runtime.h>
#include <cuda_bf16.h>
#include <math.h>
#include <stdint.h>

// ---------------- constants ----------------
#define NTOK     2048
#define HIDDEN   2880
#define HEAD_DIM 64
#define N_HEADS  64
#define N_KV     8
#define Q_MULT   8
#define QKV_DIM  5120      // 64*(64+16)
#define Q_DIM    4096      // 64*64
#define KV_OFF   4096
#define V_OFF    4608
#define WINDOW   128

// ---------------- scratch (no cudaMalloc allowed) ----------------
__device__ float g_QKV[NTOK * QKV_DIM];
__device__ __nv_bfloat16 g_Ahi[NTOK * Q_DIM];        // GEMM A operand, split hi
__device__ __nv_bfloat16 g_Alo[NTOK * Q_DIM];
__device__ __nv_bfloat16 g_B1hi[QKV_DIM * HIDDEN];   // qkv_w split+transposed
__device__ __nv_bfloat16 g_B1lo[QKV_DIM * HIDDEN];
__device__ __nv_bfloat16 g_B2hi[HIDDEN * Q_DIM];     // out_w split+transposed
__device__ __nv_bfloat16 g_B2lo[HIDDEN * Q_DIM];

// ---------------- helpers ----------------
__device__ __forceinline__ uint32_t smem_u32(const void* p) {
    uint32_t a;
    asm("{ .reg .u64 t; cvta.to.shared.u64 t, %1; cvt.u32.u64 %0, t; }" : "=r"(a) : "l"(p));
    return a;
}
__device__ __forceinline__ void cp16(uint32_t dst, const void* src) {
    asm volatile("cp.async.cg.shared.global [%0], [%1], 16;" :: "r"(dst), "l"(src));
}
#define CP_COMMIT() asm volatile("cp.async.commit_group;" ::: "memory")
#define CP_WAIT(n)  asm volatile("cp.async.wait_group %0;" :: "n"(n) : "memory")

__device__ __forceinline__ void ldsm_x4(uint32_t* r, uint32_t addr) {
    asm volatile("ldmatrix.sync.aligned.m8n8.x4.shared.b16 {%0,%1,%2,%3}, [%4];"
                 : "=r"(r[0]), "=r"(r[1]), "=r"(r[2]), "=r"(r[3]) : "r"(addr));
}
__device__ __forceinline__ void mma16816(float* c, const uint32_t* a, uint32_t b0, uint32_t b1) {
    asm volatile(
        "mma.sync.aligned.m16n8k16.row.col.f32.bf16.bf16.f32 "
        "{%0,%1,%2,%3}, {%4,%5,%6,%7}, {%8,%9}, {%0,%1,%2,%3};"
        : "+f"(c[0]), "+f"(c[1]), "+f"(c[2]), "+f"(c[3])
        : "r"(a[0]), "r"(a[1]), "r"(a[2]), "r"(a[3]), "r"(b0), "r"(b1));
}
__device__ __forceinline__ void split_bf16(float v, __nv_bfloat16& h, __nv_bfloat16& l) {
    h = __float2bfloat16(v);
    l = __float2bfloat16(v - __bfloat162float(h));
}
__device__ __forceinline__ uint32_t pack2(__nv_bfloat16 a, __nv_bfloat16 b) {
    __nv_bfloat162 t = __halves2bfloat162(a, b);
    return *(uint32_t*)&t;
}
__device__ __forceinline__ uint32_t pack_split(float a, float b, uint32_t* lo) {
    __nv_bfloat16 ha, la, hb, lb;
    split_bf16(a, ha, la);
    split_bf16(b, hb, lb);
    *lo = pack2(la, lb);
    return pack2(ha, hb);
}

// ---------------- RMSNorm fused with A-split ----------------
__global__ void rmsnorm_split_kernel(const float* __restrict__ x,
                                     const float* __restrict__ w,
                                     __nv_bfloat16* __restrict__ hi,
                                     __nv_bfloat16* __restrict__ lo) {
    int row = blockIdx.x;
    const float4* xr = (const float4*)(x + row * HIDDEN);
    const float4* wr = (const float4*)w;

    float s = 0.f;
    for (int i = threadIdx.x; i < HIDDEN / 4; i += 256) {
        float4 v = xr[i];
        s += v.x * v.x + v.y * v.y + v.z * v.z + v.w * v.w;
    }
    __shared__ float red[256];
    red[threadIdx.x] = s;
    __syncthreads();
    for (int off = 128; off > 0; off >>= 1) {
        if (threadIdx.x < off) red[threadIdx.x] += red[threadIdx.x + off];
        __syncthreads();
    }
    float r = rsqrtf(red[0] / (float)HIDDEN + 1e-5f);

    for (int i = threadIdx.x; i < HIDDEN / 4; i += 256) {
        float4 v = xr[i], ww = wr[i];
        float t0 = v.x * r * ww.x, t1 = v.y * r * ww.y;
        float t2 = v.z * r * ww.z, t3 = v.w * r * ww.w;
        __nv_bfloat16 h0, h1, h2, h3, l0, l1, l2, l3;
        split_bf16(t0, h0, l0); split_bf16(t1, h1, l1);
        split_bf16(t2, h2, l2); split_bf16(t3, h3, l3);
        uint2 hp, lp;
        hp.x = pack2(h0, h1); hp.y = pack2(h2, h3);
        lp.x = pack2(l0, l1); lp.y = pack2(l2, l3);
        ((uint2*)(hi + (size_t)row * HIDDEN))[i] = hp;
        ((uint2*)(lo + (size_t)row * HIDDEN))[i] = lp;
    }
}

// ---------------- split + transpose: in[K][N] fp32 -> out[N][K] bf16 hi/lo ----------------
__global__ void split_transpose_kernel(const float* __restrict__ in,
                                       __nv_bfloat16* __restrict__ hi,
                                       __nv_bfloat16* __restrict__ lo,
                                       int K, int N) {
    __shared__ float t[32][33];
    int k0 = blockIdx.y * 32, n0 = blockIdx.x * 32;
    int tx = threadIdx.x, ty = threadIdx.y;  // 32 x 8
#pragma unroll
    for (int i = 0; i < 4; i++)
        t[ty + 8 * i][tx] = in[(size_t)(k0 + ty + 8 * i) * N + n0 + tx];
    __syncthreads();
#pragma unroll
    for (int i = 0; i < 4; i++) {
        float v = t[tx][ty + 8 * i];
        __nv_bfloat16 h, l;
        split_bf16(v, h, l);
        size_t idx = (size_t)(n0 + ty + 8 * i) * K + k0 + tx;
        hi[idx] = h;
        lo[idx] = l;
    }
}

// ---------------- mma.sync split-bf16 GEMM ----------------
// CTA tile 64(M) x 128(N), K chunk 32, 2-stage cp.async (60KB smem -> 3 CTAs/SM).
// 8 warps as 2(m) x 4(n), warp tile 32x32. Row stride 80B (40 bf16, conflict-free).
#define ROWB      80
#define A_BYTES   (64 * ROWB)              // 5120
#define B_BYTES   (128 * ROWB)             // 10240
#define OFF_AHI   0
#define OFF_ALO   A_BYTES
#define OFF_BHI   (2 * A_BYTES)
#define OFF_BLO   (2 * A_BYTES + B_BYTES)
#define STG_BYTES (2 * A_BYTES + 2 * B_BYTES)   // 30720
#define GEMM_SMEM (2 * STG_BYTES)               // 61440

template <bool RESID>
__global__ void __launch_bounds__(256, 3) gemm_mma(
    const __nv_bfloat16* __restrict__ Ahi, const __nv_bfloat16* __restrict__ Alo,
    const __nv_bfloat16* __restrict__ Bhi, const __nv_bfloat16* __restrict__ Blo,
    const float* __restrict__ R, float* __restrict__ C, int N, int K) {
    extern __shared__ char smem[];
    const uint32_t sb = smem_u32(smem);
    const int tid  = threadIdx.x;
    const int warp = tid >> 5;
    const int lane = tid & 31;
    const int row0 = blockIdx.y * 64;
    const int col0 = blockIdx.x * 128;

    // loader mapping
    const int arow = tid >> 2;              // 0..63
    const int akk  = (tid & 3) * 8;         // k elem offset (8-elem segs)
    const int brw  = tid >> 1;              // 0..127
    const int bkk  = (tid & 1) * 16;        // k elem offset (16-elem segs)

    const __nv_bfloat16* pAhi = Ahi + (size_t)(row0 + arow) * K + akk;
    const __nv_bfloat16* pAlo = Alo + (size_t)(row0 + arow) * K + akk;
    int brow = (col0 + brw < N) ? (col0 + brw) : 0;
    const __nv_bfloat16* pBhi = Bhi + (size_t)brow * K + bkk;
    const __nv_bfloat16* pBlo = Blo + (size_t)brow * K + bkk;

    const uint32_t adst = sb + (uint32_t)arow * ROWB + (uint32_t)akk * 2;
    const uint32_t bdst = sb + (uint32_t)brw * ROWB + (uint32_t)bkk * 2;

    const int wm0 = (warp >> 2) * 32;       // 0 / 32
    const int wn0 = (warp & 3) * 32;        // 0..96

    const uint32_t afo = (uint32_t)(wm0 + (lane & 15)) * ROWB + ((lane >> 4) << 4);
    const uint32_t bfo = (uint32_t)(wn0 + (lane & 15)) * ROWB + ((lane >> 4) << 4);

    float acc[2][4][4];
#pragma unroll
    for (int i = 0; i < 2; i++)
#pragma unroll
        for (int j = 0; j < 4; j++)
#pragma unroll
            for (int k = 0; k < 4; k++) acc[i][j][k] = 0.f;

    const int nc = K >> 5;

    {
        cp16(adst + OFF_AHI, pAhi);
        cp16(adst + OFF_ALO, pAlo);
        cp16(bdst + OFF_BHI,      pBhi);  cp16(bdst + OFF_BHI + 16, pBhi + 8);
        cp16(bdst + OFF_BLO,      pBlo);  cp16(bdst + OFF_BLO + 16, pBlo + 8);
        CP_COMMIT();
    }

    for (int c = 0; c < nc; c++) {
        const uint32_t cur = (uint32_t)(c & 1) * STG_BYTES;
        if (c + 1 < nc) {
            const uint32_t nxt = (uint32_t)((c + 1) & 1) * STG_BYTES;
            const int ke = (c + 1) * 32;
            cp16(adst + nxt + OFF_AHI, pAhi + ke);
            cp16(adst + nxt + OFF_ALO, pAlo + ke);
            cp16(bdst + nxt + OFF_BHI,      pBhi + ke);  cp16(bdst + nxt + OFF_BHI + 16, pBhi + ke + 8);
            cp16(bdst + nxt + OFF_BLO,      pBlo + ke);  cp16(bdst + nxt + OFF_BLO + 16, pBlo + ke + 8);
            CP_COMMIT();
            CP_WAIT(1);
        } else {
            CP_WAIT(0);
        }
        __syncthreads();

#pragma unroll
        for (int ks = 0; ks < 2; ks++) {
            const uint32_t ko = (uint32_t)ks * 32;
            uint32_t ah[2][4], al[2][4];
#pragma unroll
            for (int mt = 0; mt < 2; mt++) {
                ldsm_x4(ah[mt], sb + cur + OFF_AHI + afo + mt * (16 * ROWB) + ko);
                ldsm_x4(al[mt], sb + cur + OFF_ALO + afo + mt * (16 * ROWB) + ko);
            }
#pragma unroll
            for (int np = 0; np < 2; np++) {
                uint32_t bh[4], bl[4];
                const uint32_t bo = bfo + np * (16 * ROWB) + ko;
                ldsm_x4(bh, sb + cur + OFF_BHI + bo);
                ldsm_x4(bl, sb + cur + OFF_BLO + bo);
#pragma unroll
                for (int mt = 0; mt < 2; mt++) {
#pragma unroll
                    for (int h2 = 0; h2 < 2; h2++) {
                        const int nt = np * 2 + h2;
                        mma16816(acc[mt][nt], ah[mt], bh[h2], bh[h2 + 2]);
                        mma16816(acc[mt][nt], ah[mt], bl[h2], bl[h2 + 2]);
                        mma16816(acc[mt][nt], al[mt], bh[h2], bh[h2 + 2]);
                    }
                }
            }
        }
        __syncthreads();
    }

    const int g = lane >> 2, cq = lane & 3;
#pragma unroll
    for (int mt = 0; mt < 2; mt++) {
#pragma unroll
        for (int nt = 0; nt < 4; nt++) {
            const int col = col0 + wn0 + nt * 8 + cq * 2;
            if (col < N) {
                const int m0 = row0 + wm0 + mt * 16 + g;
                float2 v0 = make_float2(acc[mt][nt][0], acc[mt][nt][1]);
                float2 v1 = make_float2(acc[mt][nt][2], acc[mt][nt][3]);
                if (RESID) {
                    float2 r0 = *(const float2*)(R + (size_t)m0 * N + col);
                    float2 r1 = *(const float2*)(R + (size_t)(m0 + 8) * N + col);
                    v0.x += r0.x; v0.y += r0.y; v1.x += r1.x; v1.y += r1.y;
                }
                *(float2*)(C + (size_t)m0 * N + col) = v0;
                *(float2*)(C + (size_t)(m0 + 8) * N + col) = v1;
            }
        }
    }
}

// ---------------- RoPE (YaRN/NTK) in place on Q and K ----------------
__global__ void rope_kernel(float* __restrict__ qkv) {
    int i = blockIdx.x;
    __shared__ float s_cos[32], s_sin[32];
    int tid = threadIdx.x;
    if (tid < 32) {
        float d   = (float)tid;
        float lnB = logf(150000.0f);
        float freq = expf(lnB * d / 32.0f);
        float low  = 32.0f * logf(4096.0f / (32.0f * 6.2831853071795864f)) / lnB;
        float high = 32.0f * logf(4096.0f / (6.2831853071795864f)) / lnB;
        float interp = 1.0f / (32.0f * freq);
        float extrap = 1.0f / freq;
        float ramp = (d - low) / (high - low);
        float mask = 1.0f - fminf(fmaxf(ramp, 0.0f), 1.0f);
        float inv  = interp * (1.0f - mask) + extrap * mask;
        float conc = 0.1f * logf(32.0f) + 1.0f;
        float ang  = (float)i * inv;
        s_cos[tid] = cosf(ang) * conc;
        s_sin[tid] = sinf(ang) * conc;
    }
    __syncthreads();
    float* base = qkv + (size_t)i * QKV_DIM;
    for (int idx = tid; idx < 72 * 32; idx += blockDim.x) {
        int head = idx >> 5;
        int d    = idx & 31;
        float* p = (head < 64) ? (base + head * 64)
                               : (base + KV_OFF + (head - 64) * 64);
        float x1 = p[d], x2 = p[d + 32];
        float c = s_cos[d], s = s_sin[d];
        p[d]      = x1 * c - x2 * s;
        p[d + 32] = x2 * c + x1 * s;
    }
}

// ---------------- MMA sliding-window attention with sink (verified R8) ----------------
#define NC        160
#define SRQ       144
#define SRVT      336
#define AOFF_QHI  0
#define AOFF_QLO  9216
#define AOFF_KHI  18432
#define AOFF_KLO  41472
#define AOFF_VHI  64512
#define AOFF_VLO  86016
#define AOFF_O    107520
#define AOFF_SM   124928
#define AOFF_SS   125440
#define AOFF_DEN  125952
#define ATTN_SMEM 126208

__global__ void __launch_bounds__(256, 1) attn_mma_kernel(
    const float* __restrict__ qkv, const float* __restrict__ sinks,
    __nv_bfloat16* __restrict__ ohi, __nv_bfloat16* __restrict__ olo) {
    extern __shared__ char smem[];
    const uint32_t sb = smem_u32(smem);
    const int tid  = threadIdx.x;
    const int warp = tid >> 5;
    const int lane = tid & 31;
    const int t0   = blockIdx.x * 8;
    const int kv   = blockIdx.y;
    const int j0   = (t0 >= 128) ? (t0 - 127) : 0;
    const int jmax = t0 + 7;
    const float NEGINF = __int_as_float(0xff800000);

    if (tid < 128) {
        int r = tid >> 1, hf = tid & 1;
        int i = t0 + (r & 7);
        int h = kv * 8 + (r >> 3);
        const float4* src = (const float4*)(qkv + (size_t)i * QKV_DIM + h * 64 + hf * 32);
        char* dh = smem + AOFF_QHI + r * SRQ + hf * 64;
        char* dl = smem + AOFF_QLO + r * SRQ + hf * 64;
#pragma unroll
        for (int u = 0; u < 8; u++) {
            float4 v = src[u];
            __nv_bfloat16 h0, h1, h2, h3, l0, l1, l2, l3;
            split_bf16(v.x * 0.125f, h0, l0); split_bf16(v.y * 0.125f, h1, l1);
            split_bf16(v.z * 0.125f, h2, l2); split_bf16(v.w * 0.125f, h3, l3);
            *(uint2*)(dh + u * 8) = make_uint2(pack2(h0, h1), pack2(h2, h3));
            *(uint2*)(dl + u * 8) = make_uint2(pack2(l0, l1), pack2(l2, l3));
        }
    }
    for (int idx = tid; idx < NC * 2; idx += 256) {
        int c = idx >> 1, hf = idx & 1;
        int j = j0 + c;
        bool ok = (j <= jmax);
        const float4* src = (const float4*)(qkv + (size_t)j * QKV_DIM + KV_OFF + kv * 64 + hf * 32);
        char* dh = smem + AOFF_KHI + c * SRQ + hf * 64;
        char* dl = smem + AOFF_KLO + c * SRQ + hf * 64;
#pragma unroll
        for (int u = 0; u < 8; u++) {
            float4 v = make_float4(0.f, 0.f, 0.f, 0.f);
            if (ok) v = src[u];
            __nv_bfloat16 h0, h1, h2, h3, l0, l1, l2, l3;
            split_bf16(v.x, h0, l0); split_bf16(v.y, h1, l1);
            split_bf16(v.z, h2, l2); split_bf16(v.w, h3, l3);
            *(uint2*)(dh + u * 8) = make_uint2(pack2(h0, h1), pack2(h2, h3));
            *(uint2*)(dl + u * 8) = make_uint2(pack2(l0, l1), pack2(l2, l3));
        }
    }
    if (tid < 80) {
        int p = tid;
        int ja = j0 + 2 * p, jb = ja + 1;
        bool oka = (ja <= jmax), okb = (jb <= jmax);
        const float4* sa = (const float4*)(qkv + (size_t)ja * QKV_DIM + V_OFF + kv * 64);
        const float4* sv = (const float4*)(qkv + (size_t)jb * QKV_DIM + V_OFF + kv * 64);
#pragma unroll
        for (int d4 = 0; d4 < 16; d4++) {
            float4 va = make_float4(0.f, 0.f, 0.f, 0.f);
            float4 vb = make_float4(0.f, 0.f, 0.f, 0.f);
            if (oka) va = sa[d4];
            if (okb) vb = sv[d4];
            float fa[4] = {va.x, va.y, va.z, va.w};
            float fb[4] = {vb.x, vb.y, vb.z, vb.w};
#pragma unroll
            for (int e = 0; e < 4; e++) {
                int d = d4 * 4 + e;
                __nv_bfloat16 ha, la, hb, lb;
                split_bf16(fa[e], ha, la);
                split_bf16(fb[e], hb, lb);
                *(uint32_t*)(smem + AOFF_VHI + d * SRVT + p * 4) = pack2(ha, hb);
                *(uint32_t*)(smem + AOFF_VLO + d * SRVT + p * 4) = pack2(la, lb);
            }
        }
    }
    __syncthreads();

    const int wm = warp >> 1, wn = warp & 1;
    const int wm0 = wm * 16;
    const int g = lane >> 2, q = lane & 3;

    float acc[10][4];
#pragma unroll
    for (int nt = 0; nt < 10; nt++)
#pragma unroll
        for (int e = 0; e < 4; e++) acc[nt][e] = 0.f;

    const uint32_t aoff = (uint32_t)(wm0 + (lane & 15)) * SRQ + ((lane >> 4) << 4);
#pragma unroll
    for (int kc = 0; kc < 4; kc++) {
        uint32_t qh[4], ql[4];
        ldsm_x4(qh, sb + AOFF_QHI + aoff + kc * 32);
        ldsm_x4(ql, sb + AOFF_QLO + aoff + kc * 32);
#pragma unroll
        for (int np = 0; np < 5; np++) {
            uint32_t bh[4], bl[4];
            uint32_t boff = (uint32_t)(wn * 80 + np * 16 + (lane & 15)) * SRQ
                          + ((lane >> 4) << 4) + kc * 32;
            ldsm_x4(bh, sb + AOFF_KHI + boff);
            ldsm_x4(bl, sb + AOFF_KLO + boff);
#pragma unroll
            for (int h2 = 0; h2 < 2; h2++) {
                const int nt = np * 2 + h2;
                mma16816(acc[nt], qh, bh[h2], bh[h2 + 2]);
                mma16816(acc[nt], qh, bl[h2], bl[h2 + 2]);
                mma16816(acc[nt], ql, bh[h2], bh[h2 + 2]);
            }
        }
    }

    const int lo_c = (t0 >= 128) ? g : 0;
    const int hi_c = (t0 >= 128) ? (127 + g) : (t0 + g);
    bool val0[10], val1[10];
    float vmax0 = NEGINF, vmax1 = NEGINF;
#pragma unroll
    for (int nt = 0; nt < 10; nt++) {
        int c0 = wn * 80 + nt * 8 + q * 2;
        int c1 = c0 + 1;
        val0[nt] = (c0 >= lo_c) && (c0 <= hi_c);
        val1[nt] = (c1 >= lo_c) && (c1 <= hi_c);
        if (val0[nt]) { vmax0 = fmaxf(vmax0, acc[nt][0]); vmax1 = fmaxf(vmax1, acc[nt][2]); }
        if (val1[nt]) { vmax0 = fmaxf(vmax0, acc[nt][1]); vmax1 = fmaxf(vmax1, acc[nt][3]); }
    }
    vmax0 = fmaxf(vmax0, __shfl_xor_sync(0xffffffffu, vmax0, 1));
    vmax0 = fmaxf(vmax0, __shfl_xor_sync(0xffffffffu, vmax0, 2));
    vmax1 = fmaxf(vmax1, __shfl_xor_sync(0xffffffffu, vmax1, 1));
    vmax1 = fmaxf(vmax1, __shfl_xor_sync(0xffffffffu, vmax1, 2));
    float* sM = (float*)(smem + AOFF_SM);
    if (q == 0) { sM[wn * 64 + wm0 + g] = vmax0; sM[wn * 64 + wm0 + g + 8] = vmax1; }
    __syncthreads();

    const float snk0 = sinks[kv * 8 + 2 * wm];
    const float snk1 = sinks[kv * 8 + 2 * wm + 1];
    const float m0 = fmaxf(fmaxf(sM[wm0 + g], sM[64 + wm0 + g]), snk0);
    const float m1 = fmaxf(fmaxf(sM[wm0 + g + 8], sM[64 + wm0 + g + 8]), snk1);
    float sum0 = 0.f, sum1 = 0.f;
#pragma unroll
    for (int nt = 0; nt < 10; nt++) {
        acc[nt][0] = val0[nt] ? __expf(acc[nt][0] - m0) : 0.f;
        acc[nt][1] = val1[nt] ? __expf(acc[nt][1] - m0) : 0.f;
        acc[nt][2] = val0[nt] ? __expf(acc[nt][2] - m1) : 0.f;
        acc[nt][3] = val1[nt] ? __expf(acc[nt][3] - m1) : 0.f;
        sum0 += acc[nt][0] + acc[nt][1];
        sum1 += acc[nt][2] + acc[nt][3];
    }
    sum0 += __shfl_xor_sync(0xffffffffu, sum0, 1);
    sum0 += __shfl_xor_sync(0xffffffffu, sum0, 2);
    sum1 += __shfl_xor_sync(0xffffffffu, sum1, 1);
    sum1 += __shfl_xor_sync(0xffffffffu, sum1, 2);
    float* sS = (float*)(smem + AOFF_SS);
    if (q == 0) { sS[wn * 64 + wm0 + g] = sum0; sS[wn * 64 + wm0 + g + 8] = sum1; }
    __syncthreads();

    float* sDen = (float*)(smem + AOFF_DEN);
    if (wn == 0 && q == 0) {
        int r0 = wm0 + g, r1 = r0 + 8;
        sDen[r0] = 1.f / (sS[r0] + sS[64 + r0] + __expf(snk0 - m0));
        sDen[r1] = 1.f / (sS[r1] + sS[64 + r1] + __expf(snk1 - m1));
    }

    float accO[8][4];
#pragma unroll
    for (int nt = 0; nt < 8; nt++)
#pragma unroll
        for (int e = 0; e < 4; e++) accO[nt][e] = 0.f;

#pragma unroll
    for (int kc = 0; kc < 5; kc++) {
        uint32_t ah[4], al[4];
        ah[0] = pack_split(acc[2 * kc][0],     acc[2 * kc][1],     &al[0]);
        ah[1] = pack_split(acc[2 * kc][2],     acc[2 * kc][3],     &al[1]);
        ah[2] = pack_split(acc[2 * kc + 1][0], acc[2 * kc + 1][1], &al[2]);
        ah[3] = pack_split(acc[2 * kc + 1][2], acc[2 * kc + 1][3], &al[3]);
#pragma unroll
        for (int np = 0; np < 4; np++) {
            uint32_t bh[4], bl[4];
            uint32_t boff = (uint32_t)(np * 16 + (lane & 15)) * SRVT
                          + ((lane >> 4) << 4) + wn * 160 + kc * 32;
            ldsm_x4(bh, sb + AOFF_VHI + boff);
            ldsm_x4(bl, sb + AOFF_VLO + boff);
#pragma unroll
            for (int h2 = 0; h2 < 2; h2++) {
                const int nt = np * 2 + h2;
                mma16816(accO[nt], ah, bh[h2], bh[h2 + 2]);
                mma16816(accO[nt], ah, bl[h2], bl[h2 + 2]);
                mma16816(accO[nt], al, bh[h2], bh[h2 + 2]);
            }
        }
    }

    float* sO = (float*)(smem + AOFF_O);
    if (wn == 0) {
#pragma unroll
        for (int nt = 0; nt < 8; nt++) {
            int c = nt * 8 + q * 2;
            *(float2*)&sO[(wm0 + g) * 68 + c]     = make_float2(accO[nt][0], accO[nt][1]);
            *(float2*)&sO[(wm0 + g + 8) * 68 + c] = make_float2(accO[nt][2], accO[nt][3]);
        }
    }
    __syncthreads();
    if (wn == 1) {
#pragma unroll
        for (int nt = 0; nt < 8; nt++) {
            int c = nt * 8 + q * 2;
            float2 a = *(float2*)&sO[(wm0 + g) * 68 + c];
            a.x += accO[nt][0]; a.y += accO[nt][1];
            *(float2*)&sO[(wm0 + g) * 68 + c] = a;
            float2 b = *(float2*)&sO[(wm0 + g + 8) * 68 + c];
            b.x += accO[nt][2]; b.y += accO[nt][3];
            *(float2*)&sO[(wm0 + g + 8) * 68 + c] = b;
        }
    }
    __syncthreads();

    for (int idx = tid; idx < 4096; idx += 256) {
        int r = idx >> 6, d = idx & 63;
        float v = sO[r * 68 + d] * sDen[r];
        int i = t0 + (r & 7);
        int col = kv * 512 + (r >> 3) * 64 + d;
        __nv_bfloat16 h, l;
        split_bf16(v, h, l);
        ohi[(size_t)i * Q_DIM + col] = h;
        olo[(size_t)i * Q_DIM + col] = l;
    }
}

// ---------------- launch ----------------
extern "C" void kernel_launch(void* const* d_in, const int* in_sizes, int n_in,
                              void* d_out, int out_size) {
    const float* x      = (const float*)d_in[0];
    const float* norm_w = (const float*)d_in[1];
    const float* qkv_w  = (const float*)d_in[2];
    const float* out_w  = (const float*)d_in[3];
    const float* sinks  = (const float*)d_in[4];
    float* out = (float*)d_out;

    float* QKV;
    __nv_bfloat16 *Ahi, *Alo, *B1hi, *B1lo, *B2hi, *B2lo;
    cudaGetSymbolAddress((void**)&QKV,  g_QKV);
    cudaGetSymbolAddress((void**)&Ahi,  g_Ahi);
    cudaGetSymbolAddress((void**)&Alo,  g_Alo);
    cudaGetSymbolAddress((void**)&B1hi, g_B1hi);
    cudaGetSymbolAddress((void**)&B1lo, g_B1lo);
    cudaGetSymbolAddress((void**)&B2hi, g_B2hi);
    cudaGetSymbolAddress((void**)&B2lo, g_B2lo);

    cudaFuncSetAttribute(gemm_mma<false>, cudaFuncAttributeMaxDynamicSharedMemorySize, GEMM_SMEM);
    cudaFuncSetAttribute(gemm_mma<true>,  cudaFuncAttributeMaxDynamicSharedMemorySize, GEMM_SMEM);
    cudaFuncSetAttribute(attn_mma_kernel, cudaFuncAttributeMaxDynamicSharedMemorySize, ATTN_SMEM);

    // 1. RMSNorm fused with A-split
    rmsnorm_split_kernel<<<NTOK, 256>>>(x, norm_w, Ahi, Alo);

    // 2. split+transpose qkv_w [2880][5120] -> B1 [5120][2880]
    {
        dim3 grid(QKV_DIM / 32, HIDDEN / 32);
        split_transpose_kernel<<<grid, dim3(32, 8)>>>(qkv_w, B1hi, B1lo, HIDDEN, QKV_DIM);
    }

    // 3. split+transpose out_w [4096][2880] -> B2 [2880][4096]
    {
        dim3 grid(HIDDEN / 32, Q_DIM / 32);
        split_transpose_kernel<<<grid, dim3(32, 8)>>>(out_w, B2hi, B2lo, Q_DIM, HIDDEN);
    }

    // 4. QKV GEMM (launch #4 -> ncu profiles this one)
    {
        dim3 grid(QKV_DIM / 128, NTOK / 64);
        gemm_mma<false><<<grid, 256, GEMM_SMEM>>>(Ahi, Alo, B1hi, B1lo, nullptr, QKV,
                                                  QKV_DIM, HIDDEN);
    }

    // 5. RoPE
    rope_kernel<<<NTOK, 256>>>(QKV);

    // 6. MMA attention (writes split bf16 A for GEMM2 directly)
    {
        dim3 grid(NTOK / 8, N_KV);
        attn_mma_kernel<<<grid, 256, ATTN_SMEM>>>(QKV, sinks, Ahi, Alo);
    }

    // 7. out projection + residual
    {
        dim3 grid((HIDDEN + 127) / 128, NTOK / 64);
        gemm_mma<true><<<grid, 256, GEMM_SMEM>>>(Ahi, Alo, B2hi, B2lo, x, out,
                                                 HIDDEN, Q_DIM);
    }
}

// round 12
// speedup vs baseline: 1.8188x; 1.4440x over previous
#include <cuda_runtime.h>
#include <cuda_bf16.h>
#include <cuda_fp16.h>
#include <math.h>
#include <stdint.h>

// ---------------- constants ----------------
#define NTOK     2048
#define HIDDEN   2880
#define HEAD_DIM 64
#define N_HEADS  64
#define N_KV     8
#define Q_MULT   8
#define QKV_DIM  5120      // 64*(64+16)
#define Q_DIM    4096      // 64*64
#define KV_OFF   4096
#define V_OFF    4608
#define WINDOW   128

// ---------------- scratch (no cudaMalloc allowed) ----------------
__device__ float g_QKV[NTOK * QKV_DIM];
__device__ __half g_Ahi[NTOK * Q_DIM];        // GEMM A operand, fp16 hi
__device__ __half g_Alo[NTOK * Q_DIM];        // fp16 residual
__device__ __half g_B1[QKV_DIM * HIDDEN];     // qkv_w fp16, transposed (K-major)
__device__ __half g_B2[HIDDEN * Q_DIM];       // out_w fp16, transposed

// ---------------- helpers ----------------
__device__ __forceinline__ uint32_t smem_u32(const void* p) {
    uint32_t a;
    asm("{ .reg .u64 t; cvta.to.shared.u64 t, %1; cvt.u32.u64 %0, t; }" : "=r"(a) : "l"(p));
    return a;
}
__device__ __forceinline__ void cp16(uint32_t dst, const void* src) {
    asm volatile("cp.async.cg.shared.global [%0], [%1], 16;" :: "r"(dst), "l"(src));
}
#define CP_COMMIT() asm volatile("cp.async.commit_group;" ::: "memory")
#define CP_WAIT(n)  asm volatile("cp.async.wait_group %0;" :: "n"(n) : "memory")

__device__ __forceinline__ void ldsm_x4(uint32_t* r, uint32_t addr) {
    asm volatile("ldmatrix.sync.aligned.m8n8.x4.shared.b16 {%0,%1,%2,%3}, [%4];"
                 : "=r"(r[0]), "=r"(r[1]), "=r"(r[2]), "=r"(r[3]) : "r"(addr));
}
// bf16 mma (attention)
__device__ __forceinline__ void mma_bf16(float* c, const uint32_t* a, uint32_t b0, uint32_t b1) {
    asm volatile(
        "mma.sync.aligned.m16n8k16.row.col.f32.bf16.bf16.f32 "
        "{%0,%1,%2,%3}, {%4,%5,%6,%7}, {%8,%9}, {%0,%1,%2,%3};"
        : "+f"(c[0]), "+f"(c[1]), "+f"(c[2]), "+f"(c[3])
        : "r"(a[0]), "r"(a[1]), "r"(a[2]), "r"(a[3]), "r"(b0), "r"(b1));
}
// fp16 mma (GEMMs)
__device__ __forceinline__ void mma_f16(float* c, const uint32_t* a, uint32_t b0, uint32_t b1) {
    asm volatile(
        "mma.sync.aligned.m16n8k16.row.col.f32.f16.f16.f32 "
        "{%0,%1,%2,%3}, {%4,%5,%6,%7}, {%8,%9}, {%0,%1,%2,%3};"
        : "+f"(c[0]), "+f"(c[1]), "+f"(c[2]), "+f"(c[3])
        : "r"(a[0]), "r"(a[1]), "r"(a[2]), "r"(a[3]), "r"(b0), "r"(b1));
}
__device__ __forceinline__ void split_bf16(float v, __nv_bfloat16& h, __nv_bfloat16& l) {
    h = __float2bfloat16(v);
    l = __float2bfloat16(v - __bfloat162float(h));
}
__device__ __forceinline__ void split_f16(float v, __half& h, __half& l) {
    h = __float2half_rn(v);
    l = __float2half_rn(v - __half2float(h));
}
__device__ __forceinline__ uint32_t pack2b(__nv_bfloat16 a, __nv_bfloat16 b) {
    __nv_bfloat162 t = __halves2bfloat162(a, b);
    return *(uint32_t*)&t;
}
__device__ __forceinline__ uint32_t pack2h(__half a, __half b) {
    __half2 t = __halves2half2(a, b);
    return *(uint32_t*)&t;
}
__device__ __forceinline__ uint32_t pack_split_b(float a, float b, uint32_t* lo) {
    __nv_bfloat16 ha, la, hb, lb;
    split_bf16(a, ha, la);
    split_bf16(b, hb, lb);
    *lo = pack2b(la, lb);
    return pack2b(ha, hb);
}

// ---------------- RMSNorm fused with fp16 A-split ----------------
__global__ void rmsnorm_split_kernel(const float* __restrict__ x,
                                     const float* __restrict__ w,
                                     __half* __restrict__ hi,
                                     __half* __restrict__ lo) {
    int row = blockIdx.x;
    const float4* xr = (const float4*)(x + row * HIDDEN);
    const float4* wr = (const float4*)w;

    float s = 0.f;
    for (int i = threadIdx.x; i < HIDDEN / 4; i += 256) {
        float4 v = xr[i];
        s += v.x * v.x + v.y * v.y + v.z * v.z + v.w * v.w;
    }
    __shared__ float red[256];
    red[threadIdx.x] = s;
    __syncthreads();
    for (int off = 128; off > 0; off >>= 1) {
        if (threadIdx.x < off) red[threadIdx.x] += red[threadIdx.x + off];
        __syncthreads();
    }
    float r = rsqrtf(red[0] / (float)HIDDEN + 1e-5f);

    for (int i = threadIdx.x; i < HIDDEN / 4; i += 256) {
        float4 v = xr[i], ww = wr[i];
        float t0 = v.x * r * ww.x, t1 = v.y * r * ww.y;
        float t2 = v.z * r * ww.z, t3 = v.w * r * ww.w;
        __half h0, h1, h2, h3, l0, l1, l2, l3;
        split_f16(t0, h0, l0); split_f16(t1, h1, l1);
        split_f16(t2, h2, l2); split_f16(t3, h3, l3);
        uint2 hp, lp;
        hp.x = pack2h(h0, h1); hp.y = pack2h(h2, h3);
        lp.x = pack2h(l0, l1); lp.y = pack2h(l2, l3);
        ((uint2*)(hi + (size_t)row * HIDDEN))[i] = hp;
        ((uint2*)(lo + (size_t)row * HIDDEN))[i] = lp;
    }
}

// ---------------- transpose + fp16 convert: in[K][N] fp32 -> out[N][K] fp16 ----------------
__global__ void trans_f16_kernel(const float* __restrict__ in,
                                 __half* __restrict__ outp,
                                 int K, int N) {
    __shared__ float t[32][33];
    int k0 = blockIdx.y * 32, n0 = blockIdx.x * 32;
    int tx = threadIdx.x, ty = threadIdx.y;  // 32 x 8
#pragma unroll
    for (int i = 0; i < 4; i++)
        t[ty + 8 * i][tx] = in[(size_t)(k0 + ty + 8 * i) * N + n0 + tx];
    __syncthreads();
#pragma unroll
    for (int i = 0; i < 4; i++) {
        float v = t[tx][ty + 8 * i];
        outp[(size_t)(n0 + ty + 8 * i) * K + k0 + tx] = __float2half_rn(v);
    }
}

// ---------------- mma.sync fp16 GEMM (A 2-term split, B single) ----------------
// CTA tile 64(M) x 128(N), K chunk 32, 2-stage cp.async (40KB smem -> 3 CTAs/SM).
// 8 warps as 2(m) x 4(n), warp tile 32x32. Row stride 80B (40 f16, conflict-free).
#define ROWB      80
#define A_BYTES   (64 * ROWB)              // 5120
#define B_BYTES   (128 * ROWB)             // 10240
#define OFF_AHI   0
#define OFF_ALO   A_BYTES
#define OFF_B     (2 * A_BYTES)
#define STG_BYTES (2 * A_BYTES + B_BYTES)  // 20480
#define GEMM_SMEM (2 * STG_BYTES)          // 40960

template <bool RESID>
__global__ void __launch_bounds__(256, 3) gemm_mma(
    const __half* __restrict__ Ahi, const __half* __restrict__ Alo,
    const __half* __restrict__ B,
    const float* __restrict__ R, float* __restrict__ C, int N, int K) {
    extern __shared__ char smem[];
    const uint32_t sb = smem_u32(smem);
    const int tid  = threadIdx.x;
    const int warp = tid >> 5;
    const int lane = tid & 31;
    const int row0 = blockIdx.y * 64;
    const int col0 = blockIdx.x * 128;

    const int arow = tid >> 2;              // 0..63
    const int akk  = (tid & 3) * 8;
    const int brw  = tid >> 1;              // 0..127
    const int bkk  = (tid & 1) * 16;

    const __half* pAhi = Ahi + (size_t)(row0 + arow) * K + akk;
    const __half* pAlo = Alo + (size_t)(row0 + arow) * K + akk;
    int brow = (col0 + brw < N) ? (col0 + brw) : 0;
    const __half* pB = B + (size_t)brow * K + bkk;

    const uint32_t adst = sb + (uint32_t)arow * ROWB + (uint32_t)akk * 2;
    const uint32_t bdst = sb + (uint32_t)brw * ROWB + (uint32_t)bkk * 2;

    const int wm0 = (warp >> 2) * 32;
    const int wn0 = (warp & 3) * 32;

    const uint32_t afo = (uint32_t)(wm0 + (lane & 15)) * ROWB + ((lane >> 4) << 4);
    const uint32_t bfo = (uint32_t)(wn0 + (lane & 15)) * ROWB + ((lane >> 4) << 4);

    float acc[2][4][4];
#pragma unroll
    for (int i = 0; i < 2; i++)
#pragma unroll
        for (int j = 0; j < 4; j++)
#pragma unroll
            for (int k = 0; k < 4; k++) acc[i][j][k] = 0.f;

    const int nc = K >> 5;

    {
        cp16(adst + OFF_AHI, pAhi);
        cp16(adst + OFF_ALO, pAlo);
        cp16(bdst + OFF_B,      pB);  cp16(bdst + OFF_B + 16, pB + 8);
        CP_COMMIT();
    }

    for (int c = 0; c < nc; c++) {
        const uint32_t cur = (uint32_t)(c & 1) * STG_BYTES;
        if (c + 1 < nc) {
            const uint32_t nxt = (uint32_t)((c + 1) & 1) * STG_BYTES;
            const int ke = (c + 1) * 32;
            cp16(adst + nxt + OFF_AHI, pAhi + ke);
            cp16(adst + nxt + OFF_ALO, pAlo + ke);
            cp16(bdst + nxt + OFF_B,      pB + ke);  cp16(bdst + nxt + OFF_B + 16, pB + ke + 8);
            CP_COMMIT();
            CP_WAIT(1);
        } else {
            CP_WAIT(0);
        }
        __syncthreads();

#pragma unroll
        for (int ks = 0; ks < 2; ks++) {
            const uint32_t ko = (uint32_t)ks * 32;
            uint32_t ah[2][4], al[2][4];
#pragma unroll
            for (int mt = 0; mt < 2; mt++) {
                ldsm_x4(ah[mt], sb + cur + OFF_AHI + afo + mt * (16 * ROWB) + ko);
                ldsm_x4(al[mt], sb + cur + OFF_ALO + afo + mt * (16 * ROWB) + ko);
            }
#pragma unroll
            for (int np = 0; np < 2; np++) {
                uint32_t bh[4];
                ldsm_x4(bh, sb + cur + OFF_B + bfo + np * (16 * ROWB) + ko);
#pragma unroll
                for (int mt = 0; mt < 2; mt++) {
#pragma unroll
                    for (int h2 = 0; h2 < 2; h2++) {
                        const int nt = np * 2 + h2;
                        mma_f16(acc[mt][nt], ah[mt], bh[h2], bh[h2 + 2]);
                        mma_f16(acc[mt][nt], al[mt], bh[h2], bh[h2 + 2]);
                    }
                }
            }
        }
        __syncthreads();
    }

    const int g = lane >> 2, cq = lane & 3;
#pragma unroll
    for (int mt = 0; mt < 2; mt++) {
#pragma unroll
        for (int nt = 0; nt < 4; nt++) {
            const int col = col0 + wn0 + nt * 8 + cq * 2;
            if (col < N) {
                const int m0 = row0 + wm0 + mt * 16 + g;
                float2 v0 = make_float2(acc[mt][nt][0], acc[mt][nt][1]);
                float2 v1 = make_float2(acc[mt][nt][2], acc[mt][nt][3]);
                if (RESID) {
                    float2 r0 = *(const float2*)(R + (size_t)m0 * N + col);
                    float2 r1 = *(const float2*)(R + (size_t)(m0 + 8) * N + col);
                    v0.x += r0.x; v0.y += r0.y; v1.x += r1.x; v1.y += r1.y;
                }
                *(float2*)(C + (size_t)m0 * N + col) = v0;
                *(float2*)(C + (size_t)(m0 + 8) * N + col) = v1;
            }
        }
    }
}

// ---------------- RoPE (YaRN/NTK) in place on Q and K ----------------
__global__ void rope_kernel(float* __restrict__ qkv) {
    int i = blockIdx.x;
    __shared__ float s_cos[32], s_sin[32];
    int tid = threadIdx.x;
    if (tid < 32) {
        float d   = (float)tid;
        float lnB = logf(150000.0f);
        float freq = expf(lnB * d / 32.0f);
        float low  = 32.0f * logf(4096.0f / (32.0f * 6.2831853071795864f)) / lnB;
        float high = 32.0f * logf(4096.0f / (6.2831853071795864f)) / lnB;
        float interp = 1.0f / (32.0f * freq);
        float extrap = 1.0f / freq;
        float ramp = (d - low) / (high - low);
        float mask = 1.0f - fminf(fmaxf(ramp, 0.0f), 1.0f);
        float inv  = interp * (1.0f - mask) + extrap * mask;
        float conc = 0.1f * logf(32.0f) + 1.0f;
        float ang  = (float)i * inv;
        s_cos[tid] = cosf(ang) * conc;
        s_sin[tid] = sinf(ang) * conc;
    }
    __syncthreads();
    float* base = qkv + (size_t)i * QKV_DIM;
    for (int idx = tid; idx < 72 * 32; idx += blockDim.x) {
        int head = idx >> 5;
        int d    = idx & 31;
        float* p = (head < 64) ? (base + head * 64)
                               : (base + KV_OFF + (head - 64) * 64);
        float x1 = p[d], x2 = p[d + 32];
        float c = s_cos[d], s = s_sin[d];
        p[d]      = x1 * c - x2 * s;
        p[d + 32] = x2 * c + x1 * s;
    }
}

// ---------------- MMA sliding-window attention with sink ----------------
// Internal math unchanged (bf16 3-term, verified R8); output store -> fp16 split.
#define NC        160
#define SRQ       144
#define SRVT      336
#define AOFF_QHI  0
#define AOFF_QLO  9216
#define AOFF_KHI  18432
#define AOFF_KLO  41472
#define AOFF_VHI  64512
#define AOFF_VLO  86016
#define AOFF_O    107520
#define AOFF_SM   124928
#define AOFF_SS   125440
#define AOFF_DEN  125952
#define ATTN_SMEM 126208

__global__ void __launch_bounds__(256, 1) attn_mma_kernel(
    const float* __restrict__ qkv, const float* __restrict__ sinks,
    __half* __restrict__ ohi, __half* __restrict__ olo) {
    extern __shared__ char smem[];
    const uint32_t sb = smem_u32(smem);
    const int tid  = threadIdx.x;
    const int warp = tid >> 5;
    const int lane = tid & 31;
    const int t0   = blockIdx.x * 8;
    const int kv   = blockIdx.y;
    const int j0   = (t0 >= 128) ? (t0 - 127) : 0;
    const int jmax = t0 + 7;
    const float NEGINF = __int_as_float(0xff800000);

    if (tid < 128) {
        int r = tid >> 1, hf = tid & 1;
        int i = t0 + (r & 7);
        int h = kv * 8 + (r >> 3);
        const float4* src = (const float4*)(qkv + (size_t)i * QKV_DIM + h * 64 + hf * 32);
        char* dh = smem + AOFF_QHI + r * SRQ + hf * 64;
        char* dl = smem + AOFF_QLO + r * SRQ + hf * 64;
#pragma unroll
        for (int u = 0; u < 8; u++) {
            float4 v = src[u];
            __nv_bfloat16 h0, h1, h2, h3, l0, l1, l2, l3;
            split_bf16(v.x * 0.125f, h0, l0); split_bf16(v.y * 0.125f, h1, l1);
            split_bf16(v.z * 0.125f, h2, l2); split_bf16(v.w * 0.125f, h3, l3);
            *(uint2*)(dh + u * 8) = make_uint2(pack2b(h0, h1), pack2b(h2, h3));
            *(uint2*)(dl + u * 8) = make_uint2(pack2b(l0, l1), pack2b(l2, l3));
        }
    }
    for (int idx = tid; idx < NC * 2; idx += 256) {
        int c = idx >> 1, hf = idx & 1;
        int j = j0 + c;
        bool ok = (j <= jmax);
        const float4* src = (const float4*)(qkv + (size_t)j * QKV_DIM + KV_OFF + kv * 64 + hf * 32);
        char* dh = smem + AOFF_KHI + c * SRQ + hf * 64;
        char* dl = smem + AOFF_KLO + c * SRQ + hf * 64;
#pragma unroll
        for (int u = 0; u < 8; u++) {
            float4 v = make_float4(0.f, 0.f, 0.f, 0.f);
            if (ok) v = src[u];
            __nv_bfloat16 h0, h1, h2, h3, l0, l1, l2, l3;
            split_bf16(v.x, h0, l0); split_bf16(v.y, h1, l1);
            split_bf16(v.z, h2, l2); split_bf16(v.w, h3, l3);
            *(uint2*)(dh + u * 8) = make_uint2(pack2b(h0, h1), pack2b(h2, h3));
            *(uint2*)(dl + u * 8) = make_uint2(pack2b(l0, l1), pack2b(l2, l3));
        }
    }
    if (tid < 80) {
        int p = tid;
        int ja = j0 + 2 * p, jb = ja + 1;
        bool oka = (ja <= jmax), okb = (jb <= jmax);
        const float4* sa = (const float4*)(qkv + (size_t)ja * QKV_DIM + V_OFF + kv * 64);
        const float4* sv = (const float4*)(qkv + (size_t)jb * QKV_DIM + V_OFF + kv * 64);
#pragma unroll
        for (int d4 = 0; d4 < 16; d4++) {
            float4 va = make_float4(0.f, 0.f, 0.f, 0.f);
            float4 vb = make_float4(0.f, 0.f, 0.f, 0.f);
            if (oka) va = sa[d4];
            if (okb) vb = sv[d4];
            float fa[4] = {va.x, va.y, va.z, va.w};
            float fb[4] = {vb.x, vb.y, vb.z, vb.w};
#pragma unroll
            for (int e = 0; e < 4; e++) {
                int d = d4 * 4 + e;
                __nv_bfloat16 ha, la, hb, lb;
                split_bf16(fa[e], ha, la);
                split_bf16(fb[e], hb, lb);
                *(uint32_t*)(smem + AOFF_VHI + d * SRVT + p * 4) = pack2b(ha, hb);
                *(uint32_t*)(smem + AOFF_VLO + d * SRVT + p * 4) = pack2b(la, lb);
            }
        }
    }
    __syncthreads();

    const int wm = warp >> 1, wn = warp & 1;
    const int wm0 = wm * 16;
    const int g = lane >> 2, q = lane & 3;

    float acc[10][4];
#pragma unroll
    for (int nt = 0; nt < 10; nt++)
#pragma unroll
        for (int e = 0; e < 4; e++) acc[nt][e] = 0.f;

    const uint32_t aoff = (uint32_t)(wm0 + (lane & 15)) * SRQ + ((lane >> 4) << 4);
#pragma unroll
    for (int kc = 0; kc < 4; kc++) {
        uint32_t qh[4], ql[4];
        ldsm_x4(qh, sb + AOFF_QHI + aoff + kc * 32);
        ldsm_x4(ql, sb + AOFF_QLO + aoff + kc * 32);
#pragma unroll
        for (int np = 0; np < 5; np++) {
            uint32_t bh[4], bl[4];
            uint32_t boff = (uint32_t)(wn * 80 + np * 16 + (lane & 15)) * SRQ
                          + ((lane >> 4) << 4) + kc * 32;
            ldsm_x4(bh, sb + AOFF_KHI + boff);
            ldsm_x4(bl, sb + AOFF_KLO + boff);
#pragma unroll
            for (int h2 = 0; h2 < 2; h2++) {
                const int nt = np * 2 + h2;
                mma_bf16(acc[nt], qh, bh[h2], bh[h2 + 2]);
                mma_bf16(acc[nt], qh, bl[h2], bl[h2 + 2]);
                mma_bf16(acc[nt], ql, bh[h2], bh[h2 + 2]);
            }
        }
    }

    const int lo_c = (t0 >= 128) ? g : 0;
    const int hi_c = (t0 >= 128) ? (127 + g) : (t0 + g);
    bool val0[10], val1[10];
    float vmax0 = NEGINF, vmax1 = NEGINF;
#pragma unroll
    for (int nt = 0; nt < 10; nt++) {
        int c0 = wn * 80 + nt * 8 + q * 2;
        int c1 = c0 + 1;
        val0[nt] = (c0 >= lo_c) && (c0 <= hi_c);
        val1[nt] = (c1 >= lo_c) && (c1 <= hi_c);
        if (val0[nt]) { vmax0 = fmaxf(vmax0, acc[nt][0]); vmax1 = fmaxf(vmax1, acc[nt][2]); }
        if (val1[nt]) { vmax0 = fmaxf(vmax0, acc[nt][1]); vmax1 = fmaxf(vmax1, acc[nt][3]); }
    }
    vmax0 = fmaxf(vmax0, __shfl_xor_sync(0xffffffffu, vmax0, 1));
    vmax0 = fmaxf(vmax0, __shfl_xor_sync(0xffffffffu, vmax0, 2));
    vmax1 = fmaxf(vmax1, __shfl_xor_sync(0xffffffffu, vmax1, 1));
    vmax1 = fmaxf(vmax1, __shfl_xor_sync(0xffffffffu, vmax1, 2));
    float* sM = (float*)(smem + AOFF_SM);
    if (q == 0) { sM[wn * 64 + wm0 + g] = vmax0; sM[wn * 64 + wm0 + g + 8] = vmax1; }
    __syncthreads();

    const float snk0 = sinks[kv * 8 + 2 * wm];
    const float snk1 = sinks[kv * 8 + 2 * wm + 1];
    const float m0 = fmaxf(fmaxf(sM[wm0 + g], sM[64 + wm0 + g]), snk0);
    const float m1 = fmaxf(fmaxf(sM[wm0 + g + 8], sM[64 + wm0 + g + 8]), snk1);
    float sum0 = 0.f, sum1 = 0.f;
#pragma unroll
    for (int nt = 0; nt < 10; nt++) {
        acc[nt][0] = val0[nt] ? __expf(acc[nt][0] - m0) : 0.f;
        acc[nt][1] = val1[nt] ? __expf(acc[nt][1] - m0) : 0.f;
        acc[nt][2] = val0[nt] ? __expf(acc[nt][2] - m1) : 0.f;
        acc[nt][3] = val1[nt] ? __expf(acc[nt][3] - m1) : 0.f;
        sum0 += acc[nt][0] + acc[nt][1];
        sum1 += acc[nt][2] + acc[nt][3];
    }
    sum0 += __shfl_xor_sync(0xffffffffu, sum0, 1);
    sum0 += __shfl_xor_sync(0xffffffffu, sum0, 2);
    sum1 += __shfl_xor_sync(0xffffffffu, sum1, 1);
    sum1 += __shfl_xor_sync(0xffffffffu, sum1, 2);
    float* sS = (float*)(smem + AOFF_SS);
    if (q == 0) { sS[wn * 64 + wm0 + g] = sum0; sS[wn * 64 + wm0 + g + 8] = sum1; }
    __syncthreads();

    float* sDen = (float*)(smem + AOFF_DEN);
    if (wn == 0 && q == 0) {
        int r0 = wm0 + g, r1 = r0 + 8;
        sDen[r0] = 1.f / (sS[r0] + sS[64 + r0] + __expf(snk0 - m0));
        sDen[r1] = 1.f / (sS[r1] + sS[64 + r1] + __expf(snk1 - m1));
    }

    float accO[8][4];
#pragma unroll
    for (int nt = 0; nt < 8; nt++)
#pragma unroll
        for (int e = 0; e < 4; e++) accO[nt][e] = 0.f;

#pragma unroll
    for (int kc = 0; kc < 5; kc++) {
        uint32_t ah[4], al[4];
        ah[0] = pack_split_b(acc[2 * kc][0],     acc[2 * kc][1],     &al[0]);
        ah[1] = pack_split_b(acc[2 * kc][2],     acc[2 * kc][3],     &al[1]);
        ah[2] = pack_split_b(acc[2 * kc + 1][0], acc[2 * kc + 1][1], &al[2]);
        ah[3] = pack_split_b(acc[2 * kc + 1][2], acc[2 * kc + 1][3], &al[3]);
#pragma unroll
        for (int np = 0; np < 4; np++) {
            uint32_t bh[4], bl[4];
            uint32_t boff = (uint32_t)(np * 16 + (lane & 15)) * SRVT
                          + ((lane >> 4) << 4) + wn * 160 + kc * 32;
            ldsm_x4(bh, sb + AOFF_VHI + boff);
            ldsm_x4(bl, sb + AOFF_VLO + boff);
#pragma unroll
            for (int h2 = 0; h2 < 2; h2++) {
                const int nt = np * 2 + h2;
                mma_bf16(accO[nt], ah, bh[h2], bh[h2 + 2]);
                mma_bf16(accO[nt], ah, bl[h2], bl[h2 + 2]);
                mma_bf16(accO[nt], al, bh[h2], bh[h2 + 2]);
            }
        }
    }

    float* sO = (float*)(smem + AOFF_O);
    if (wn == 0) {
#pragma unroll
        for (int nt = 0; nt < 8; nt++) {
            int c = nt * 8 + q * 2;
            *(float2*)&sO[(wm0 + g) * 68 + c]     = make_float2(accO[nt][0], accO[nt][1]);
            *(float2*)&sO[(wm0 + g + 8) * 68 + c] = make_float2(accO[nt][2], accO[nt][3]);
        }
    }
    __syncthreads();
    if (wn == 1) {
#pragma unroll
        for (int nt = 0; nt < 8; nt++) {
            int c = nt * 8 + q * 2;
            float2 a = *(float2*)&sO[(wm0 + g) * 68 + c];
            a.x += accO[nt][0]; a.y += accO[nt][1];
            *(float2*)&sO[(wm0 + g) * 68 + c] = a;
            float2 b = *(float2*)&sO[(wm0 + g + 8) * 68 + c];
            b.x += accO[nt][2]; b.y += accO[nt][3];
            *(float2*)&sO[(wm0 + g + 8) * 68 + c] = b;
        }
    }
    __syncthreads();

    // normalize + fp16 split store (A operand of GEMM2)
    for (int idx = tid; idx < 4096; idx += 256) {
        int r = idx >> 6, d = idx & 63;
        float v = sO[r * 68 + d] * sDen[r];
        int i = t0 + (r & 7);
        int col = kv * 512 + (r >> 3) * 64 + d;
        __half h, l;
        split_f16(v, h, l);
        ohi[(size_t)i * Q_DIM + col] = h;
        olo[(size_t)i * Q_DIM + col] = l;
    }
}

// ---------------- launch ----------------
extern "C" void kernel_launch(void* const* d_in, const int* in_sizes, int n_in,
                              void* d_out, int out_size) {
    const float* x      = (const float*)d_in[0];
    const float* norm_w = (const float*)d_in[1];
    const float* qkv_w  = (const float*)d_in[2];
    const float* out_w  = (const float*)d_in[3];
    const float* sinks  = (const float*)d_in[4];
    float* out = (float*)d_out;

    float* QKV;
    __half *Ahi, *Alo, *B1, *B2;
    cudaGetSymbolAddress((void**)&QKV, g_QKV);
    cudaGetSymbolAddress((void**)&Ahi, g_Ahi);
    cudaGetSymbolAddress((void**)&Alo, g_Alo);
    cudaGetSymbolAddress((void**)&B1,  g_B1);
    cudaGetSymbolAddress((void**)&B2,  g_B2);

    cudaFuncSetAttribute(gemm_mma<false>, cudaFuncAttributeMaxDynamicSharedMemorySize, GEMM_SMEM);
    cudaFuncSetAttribute(gemm_mma<true>,  cudaFuncAttributeMaxDynamicSharedMemorySize, GEMM_SMEM);
    cudaFuncSetAttribute(attn_mma_kernel, cudaFuncAttributeMaxDynamicSharedMemorySize, ATTN_SMEM);

    // 1. RMSNorm fused with fp16 A-split
    rmsnorm_split_kernel<<<NTOK, 256>>>(x, norm_w, Ahi, Alo);

    // 2. transpose qkv_w [2880][5120] -> B1 [5120][2880] fp16
    {
        dim3 grid(QKV_DIM / 32, HIDDEN / 32);
        trans_f16_kernel<<<grid, dim3(32, 8)>>>(qkv_w, B1, HIDDEN, QKV_DIM);
    }

    // 3. transpose out_w [4096][2880] -> B2 [2880][4096] fp16
    {
        dim3 grid(HIDDEN / 32, Q_DIM / 32);
        trans_f16_kernel<<<grid, dim3(32, 8)>>>(out_w, B2, Q_DIM, HIDDEN);
    }

    // 4. QKV GEMM (launch #4 -> ncu profiles this one)
    {
        dim3 grid(QKV_DIM / 128, NTOK / 64);
        gemm_mma<false><<<grid, 256, GEMM_SMEM>>>(Ahi, Alo, B1, nullptr, QKV,
                                                  QKV_DIM, HIDDEN);
    }

    // 5. RoPE
    rope_kernel<<<NTOK, 256>>>(QKV);

    // 6. MMA attention (writes fp16 split A for GEMM2)
    {
        dim3 grid(NTOK / 8, N_KV);
        attn_mma_kernel<<<grid, 256, ATTN_SMEM>>>(QKV, sinks, Ahi, Alo);
    }

    // 7. out projection + residual
    {
        dim3 grid((HIDDEN + 127) / 128, NTOK / 64);
        gemm_mma<true><<<grid, 256, GEMM_SMEM>>>(Ahi, Alo, B2, x, out,
                                                 HIDDEN, Q_DIM);
    }
}

// round 13
// speedup vs baseline: 2.5504x; 1.4023x over previous
#include <cuda_runtime.h>
#include <cuda_bf16.h>
#include <cuda_fp16.h>
#include <math.h>
#include <stdint.h>

// ---------------- constants ----------------
#define NTOK     2048
#define HIDDEN   2880
#define HEAD_DIM 64
#define N_HEADS  64
#define N_KV     8
#define Q_MULT   8
#define QKV_DIM  5120      // 64*(64+16)
#define Q_DIM    4096      // 64*64
#define KV_OFF   4096
#define V_OFF    4608
#define WINDOW   128

// ---------------- scratch (no cudaMalloc allowed) ----------------
__device__ float g_QKV[NTOK * QKV_DIM];
__device__ __half g_A[NTOK * Q_DIM];          // GEMM A operand fp16
__device__ __half g_B1[QKV_DIM * HIDDEN];     // qkv_w fp16, transposed (K-major)
__device__ __half g_B2[HIDDEN * Q_DIM];       // out_w fp16, transposed

// ---------------- helpers ----------------
__device__ __forceinline__ uint32_t smem_u32(const void* p) {
    uint32_t a;
    asm("{ .reg .u64 t; cvta.to.shared.u64 t, %1; cvt.u32.u64 %0, t; }" : "=r"(a) : "l"(p));
    return a;
}
__device__ __forceinline__ void cp16(uint32_t dst, const void* src) {
    asm volatile("cp.async.cg.shared.global [%0], [%1], 16;" :: "r"(dst), "l"(src));
}
#define CP_COMMIT() asm volatile("cp.async.commit_group;" ::: "memory")
#define CP_WAIT(n)  asm volatile("cp.async.wait_group %0;" :: "n"(n) : "memory")

__device__ __forceinline__ void ldsm_x4(uint32_t* r, uint32_t addr) {
    asm volatile("ldmatrix.sync.aligned.m8n8.x4.shared.b16 {%0,%1,%2,%3}, [%4];"
                 : "=r"(r[0]), "=r"(r[1]), "=r"(r[2]), "=r"(r[3]) : "r"(addr));
}
// bf16 mma (attention)
__device__ __forceinline__ void mma_bf16(float* c, const uint32_t* a, uint32_t b0, uint32_t b1) {
    asm volatile(
        "mma.sync.aligned.m16n8k16.row.col.f32.bf16.bf16.f32 "
        "{%0,%1,%2,%3}, {%4,%5,%6,%7}, {%8,%9}, {%0,%1,%2,%3};"
        : "+f"(c[0]), "+f"(c[1]), "+f"(c[2]), "+f"(c[3])
        : "r"(a[0]), "r"(a[1]), "r"(a[2]), "r"(a[3]), "r"(b0), "r"(b1));
}
// fp16 mma (GEMMs)
__device__ __forceinline__ void mma_f16(float* c, const uint32_t* a, uint32_t b0, uint32_t b1) {
    asm volatile(
        "mma.sync.aligned.m16n8k16.row.col.f32.f16.f16.f32 "
        "{%0,%1,%2,%3}, {%4,%5,%6,%7}, {%8,%9}, {%0,%1,%2,%3};"
        : "+f"(c[0]), "+f"(c[1]), "+f"(c[2]), "+f"(c[3])
        : "r"(a[0]), "r"(a[1]), "r"(a[2]), "r"(a[3]), "r"(b0), "r"(b1));
}
__device__ __forceinline__ void split_bf16(float v, __nv_bfloat16& h, __nv_bfloat16& l) {
    h = __float2bfloat16(v);
    l = __float2bfloat16(v - __bfloat162float(h));
}
__device__ __forceinline__ uint32_t pack2b(__nv_bfloat16 a, __nv_bfloat16 b) {
    __nv_bfloat162 t = __halves2bfloat162(a, b);
    return *(uint32_t*)&t;
}
__device__ __forceinline__ uint32_t pack2h(__half a, __half b) {
    __half2 t = __halves2half2(a, b);
    return *(uint32_t*)&t;
}
__device__ __forceinline__ uint32_t pack_split_b(float a, float b, uint32_t* lo) {
    __nv_bfloat16 ha, la, hb, lb;
    split_bf16(a, ha, la);
    split_bf16(b, hb, lb);
    *lo = pack2b(la, lb);
    return pack2b(ha, hb);
}

// ---------------- RMSNorm -> fp16 ----------------
__global__ void rmsnorm_f16_kernel(const float* __restrict__ x,
                                   const float* __restrict__ w,
                                   __half* __restrict__ o) {
    int row = blockIdx.x;
    const float4* xr = (const float4*)(x + row * HIDDEN);
    const float4* wr = (const float4*)w;

    float s = 0.f;
    for (int i = threadIdx.x; i < HIDDEN / 4; i += 256) {
        float4 v = xr[i];
        s += v.x * v.x + v.y * v.y + v.z * v.z + v.w * v.w;
    }
    __shared__ float red[256];
    red[threadIdx.x] = s;
    __syncthreads();
    for (int off = 128; off > 0; off >>= 1) {
        if (threadIdx.x < off) red[threadIdx.x] += red[threadIdx.x + off];
        __syncthreads();
    }
    float r = rsqrtf(red[0] / (float)HIDDEN + 1e-5f);

    for (int i = threadIdx.x; i < HIDDEN / 4; i += 256) {
        float4 v = xr[i], ww = wr[i];
        uint2 hp;
        hp.x = pack2h(__float2half_rn(v.x * r * ww.x), __float2half_rn(v.y * r * ww.y));
        hp.y = pack2h(__float2half_rn(v.z * r * ww.z), __float2half_rn(v.w * r * ww.w));
        ((uint2*)(o + (size_t)row * HIDDEN))[i] = hp;
    }
}

// ---------------- transpose + fp16 convert: in[K][N] fp32 -> out[N][K] fp16 ----------------
__global__ void trans_f16_kernel(const float* __restrict__ in,
                                 __half* __restrict__ outp,
                                 int K, int N) {
    __shared__ float t[32][33];
    int k0 = blockIdx.y * 32, n0 = blockIdx.x * 32;
    int tx = threadIdx.x, ty = threadIdx.y;  // 32 x 8
#pragma unroll
    for (int i = 0; i < 4; i++)
        t[ty + 8 * i][tx] = in[(size_t)(k0 + ty + 8 * i) * N + n0 + tx];
    __syncthreads();
#pragma unroll
    for (int i = 0; i < 4; i++) {
        float v = t[tx][ty + 8 * i];
        outp[(size_t)(n0 + ty + 8 * i) * K + k0 + tx] = __float2half_rn(v);
    }
}

// ---------------- mma.sync fp16 GEMM (single term) ----------------
// CTA tile 64(M) x 128(N), K chunk 32, 2-stage cp.async (30KB smem -> 3 CTAs/SM).
// 8 warps as 2(m) x 4(n), warp tile 32x32. Row stride 80B (40 f16, conflict-free).
#define ROWB      80
#define A_BYTES   (64 * ROWB)              // 5120
#define B_BYTES   (128 * ROWB)             // 10240
#define OFF_A     0
#define OFF_B     A_BYTES
#define STG_BYTES (A_BYTES + B_BYTES)      // 15360
#define GEMM_SMEM (2 * STG_BYTES)          // 30720

template <bool RESID>
__global__ void __launch_bounds__(256, 3) gemm_mma(
    const __half* __restrict__ A, const __half* __restrict__ B,
    const float* __restrict__ R, float* __restrict__ C, int N, int K) {
    extern __shared__ char smem[];
    const uint32_t sb = smem_u32(smem);
    const int tid  = threadIdx.x;
    const int warp = tid >> 5;
    const int lane = tid & 31;
    const int row0 = blockIdx.y * 64;
    const int col0 = blockIdx.x * 128;

    const int arow = tid >> 2;              // 0..63
    const int akk  = (tid & 3) * 8;
    const int brw  = tid >> 1;              // 0..127
    const int bkk  = (tid & 1) * 16;

    const __half* pA = A + (size_t)(row0 + arow) * K + akk;
    int brow = (col0 + brw < N) ? (col0 + brw) : 0;
    const __half* pB = B + (size_t)brow * K + bkk;

    const uint32_t adst = sb + (uint32_t)arow * ROWB + (uint32_t)akk * 2;
    const uint32_t bdst = sb + (uint32_t)brw * ROWB + (uint32_t)bkk * 2;

    const int wm0 = (warp >> 2) * 32;
    const int wn0 = (warp & 3) * 32;

    const uint32_t afo = (uint32_t)(wm0 + (lane & 15)) * ROWB + ((lane >> 4) << 4);
    const uint32_t bfo = (uint32_t)(wn0 + (lane & 15)) * ROWB + ((lane >> 4) << 4);

    float acc[2][4][4];
#pragma unroll
    for (int i = 0; i < 2; i++)
#pragma unroll
        for (int j = 0; j < 4; j++)
#pragma unroll
            for (int k = 0; k < 4; k++) acc[i][j][k] = 0.f;

    const int nc = K >> 5;

    {
        cp16(adst + OFF_A, pA);
        cp16(bdst + OFF_B,      pB);  cp16(bdst + OFF_B + 16, pB + 8);
        CP_COMMIT();
    }

    for (int c = 0; c < nc; c++) {
        const uint32_t cur = (uint32_t)(c & 1) * STG_BYTES;
        if (c + 1 < nc) {
            const uint32_t nxt = (uint32_t)((c + 1) & 1) * STG_BYTES;
            const int ke = (c + 1) * 32;
            cp16(adst + nxt + OFF_A, pA + ke);
            cp16(bdst + nxt + OFF_B,      pB + ke);  cp16(bdst + nxt + OFF_B + 16, pB + ke + 8);
            CP_COMMIT();
            CP_WAIT(1);
        } else {
            CP_WAIT(0);
        }
        __syncthreads();

#pragma unroll
        for (int ks = 0; ks < 2; ks++) {
            const uint32_t ko = (uint32_t)ks * 32;
            uint32_t ah[2][4];
#pragma unroll
            for (int mt = 0; mt < 2; mt++)
                ldsm_x4(ah[mt], sb + cur + OFF_A + afo + mt * (16 * ROWB) + ko);
#pragma unroll
            for (int np = 0; np < 2; np++) {
                uint32_t bh[4];
                ldsm_x4(bh, sb + cur + OFF_B + bfo + np * (16 * ROWB) + ko);
#pragma unroll
                for (int mt = 0; mt < 2; mt++) {
#pragma unroll
                    for (int h2 = 0; h2 < 2; h2++) {
                        mma_f16(acc[mt][np * 2 + h2], ah[mt], bh[h2], bh[h2 + 2]);
                    }
                }
            }
        }
        __syncthreads();
    }

    const int g = lane >> 2, cq = lane & 3;
#pragma unroll
    for (int mt = 0; mt < 2; mt++) {
#pragma unroll
        for (int nt = 0; nt < 4; nt++) {
            const int col = col0 + wn0 + nt * 8 + cq * 2;
            if (col < N) {
                const int m0 = row0 + wm0 + mt * 16 + g;
                float2 v0 = make_float2(acc[mt][nt][0], acc[mt][nt][1]);
                float2 v1 = make_float2(acc[mt][nt][2], acc[mt][nt][3]);
                if (RESID) {
                    float2 r0 = *(const float2*)(R + (size_t)m0 * N + col);
                    float2 r1 = *(const float2*)(R + (size_t)(m0 + 8) * N + col);
                    v0.x += r0.x; v0.y += r0.y; v1.x += r1.x; v1.y += r1.y;
                }
                *(float2*)(C + (size_t)m0 * N + col) = v0;
                *(float2*)(C + (size_t)(m0 + 8) * N + col) = v1;
            }
        }
    }
}

// ---------------- RoPE (YaRN/NTK) in place on Q and K ----------------
__global__ void rope_kernel(float* __restrict__ qkv) {
    int i = blockIdx.x;
    __shared__ float s_cos[32], s_sin[32];
    int tid = threadIdx.x;
    if (tid < 32) {
        float d   = (float)tid;
        float lnB = logf(150000.0f);
        float freq = expf(lnB * d / 32.0f);
        float low  = 32.0f * logf(4096.0f / (32.0f * 6.2831853071795864f)) / lnB;
        float high = 32.0f * logf(4096.0f / (6.2831853071795864f)) / lnB;
        float interp = 1.0f / (32.0f * freq);
        float extrap = 1.0f / freq;
        float ramp = (d - low) / (high - low);
        float mask = 1.0f - fminf(fmaxf(ramp, 0.0f), 1.0f);
        float inv  = interp * (1.0f - mask) + extrap * mask;
        float conc = 0.1f * logf(32.0f) + 1.0f;
        float ang  = (float)i * inv;
        s_cos[tid] = cosf(ang) * conc;
        s_sin[tid] = sinf(ang) * conc;
    }
    __syncthreads();
    float* base = qkv + (size_t)i * QKV_DIM;
    for (int idx = tid; idx < 72 * 32; idx += blockDim.x) {
        int head = idx >> 5;
        int d    = idx & 31;
        float* p = (head < 64) ? (base + head * 64)
                               : (base + KV_OFF + (head - 64) * 64);
        float x1 = p[d], x2 = p[d + 32];
        float c = s_cos[d], s = s_sin[d];
        p[d]      = x1 * c - x2 * s;
        p[d + 32] = x2 * c + x1 * s;
    }
}

// ---------------- MMA sliding-window attention with sink ----------------
// Internal math unchanged (bf16 3-term, verified R8); output -> plain fp16.
#define NC        160
#define SRQ       144
#define SRVT      336
#define AOFF_QHI  0
#define AOFF_QLO  9216
#define AOFF_KHI  18432
#define AOFF_KLO  41472
#define AOFF_VHI  64512
#define AOFF_VLO  86016
#define AOFF_O    107520
#define AOFF_SM   124928
#define AOFF_SS   125440
#define AOFF_DEN  125952
#define ATTN_SMEM 126208

__global__ void __launch_bounds__(256, 1) attn_mma_kernel(
    const float* __restrict__ qkv, const float* __restrict__ sinks,
    __half* __restrict__ oA) {
    extern __shared__ char smem[];
    const uint32_t sb = smem_u32(smem);
    const int tid  = threadIdx.x;
    const int warp = tid >> 5;
    const int lane = tid & 31;
    const int t0   = blockIdx.x * 8;
    const int kv   = blockIdx.y;
    const int j0   = (t0 >= 128) ? (t0 - 127) : 0;
    const int jmax = t0 + 7;
    const float NEGINF = __int_as_float(0xff800000);

    if (tid < 128) {
        int r = tid >> 1, hf = tid & 1;
        int i = t0 + (r & 7);
        int h = kv * 8 + (r >> 3);
        const float4* src = (const float4*)(qkv + (size_t)i * QKV_DIM + h * 64 + hf * 32);
        char* dh = smem + AOFF_QHI + r * SRQ + hf * 64;
        char* dl = smem + AOFF_QLO + r * SRQ + hf * 64;
#pragma unroll
        for (int u = 0; u < 8; u++) {
            float4 v = src[u];
            __nv_bfloat16 h0, h1, h2, h3, l0, l1, l2, l3;
            split_bf16(v.x * 0.125f, h0, l0); split_bf16(v.y * 0.125f, h1, l1);
            split_bf16(v.z * 0.125f, h2, l2); split_bf16(v.w * 0.125f, h3, l3);
            *(uint2*)(dh + u * 8) = make_uint2(pack2b(h0, h1), pack2b(h2, h3));
            *(uint2*)(dl + u * 8) = make_uint2(pack2b(l0, l1), pack2b(l2, l3));
        }
    }
    for (int idx = tid; idx < NC * 2; idx += 256) {
        int c = idx >> 1, hf = idx & 1;
        int j = j0 + c;
        bool ok = (j <= jmax);
        const float4* src = (const float4*)(qkv + (size_t)j * QKV_DIM + KV_OFF + kv * 64 + hf * 32);
        char* dh = smem + AOFF_KHI + c * SRQ + hf * 64;
        char* dl = smem + AOFF_KLO + c * SRQ + hf * 64;
#pragma unroll
        for (int u = 0; u < 8; u++) {
            float4 v = make_float4(0.f, 0.f, 0.f, 0.f);
            if (ok) v = src[u];
            __nv_bfloat16 h0, h1, h2, h3, l0, l1, l2, l3;
            split_bf16(v.x, h0, l0); split_bf16(v.y, h1, l1);
            split_bf16(v.z, h2, l2); split_bf16(v.w, h3, l3);
            *(uint2*)(dh + u * 8) = make_uint2(pack2b(h0, h1), pack2b(h2, h3));
            *(uint2*)(dl + u * 8) = make_uint2(pack2b(l0, l1), pack2b(l2, l3));
        }
    }
    if (tid < 80) {
        int p = tid;
        int ja = j0 + 2 * p, jb = ja + 1;
        bool oka = (ja <= jmax), okb = (jb <= jmax);
        const float4* sa = (const float4*)(qkv + (size_t)ja * QKV_DIM + V_OFF + kv * 64);
        const float4* sv = (const float4*)(qkv + (size_t)jb * QKV_DIM + V_OFF + kv * 64);
#pragma unroll
        for (int d4 = 0; d4 < 16; d4++) {
            float4 va = make_float4(0.f, 0.f, 0.f, 0.f);
            float4 vb = make_float4(0.f, 0.f, 0.f, 0.f);
            if (oka) va = sa[d4];
            if (okb) vb = sv[d4];
            float fa[4] = {va.x, va.y, va.z, va.w};
            float fb[4] = {vb.x, vb.y, vb.z, vb.w};
#pragma unroll
            for (int e = 0; e < 4; e++) {
                int d = d4 * 4 + e;
                __nv_bfloat16 ha, la, hb, lb;
                split_bf16(fa[e], ha, la);
                split_bf16(fb[e], hb, lb);
                *(uint32_t*)(smem + AOFF_VHI + d * SRVT + p * 4) = pack2b(ha, hb);
                *(uint32_t*)(smem + AOFF_VLO + d * SRVT + p * 4) = pack2b(la, lb);
            }
        }
    }
    __syncthreads();

    const int wm = warp >> 1, wn = warp & 1;
    const int wm0 = wm * 16;
    const int g = lane >> 2, q = lane & 3;

    float acc[10][4];
#pragma unroll
    for (int nt = 0; nt < 10; nt++)
#pragma unroll
        for (int e = 0; e < 4; e++) acc[nt][e] = 0.f;

    const uint32_t aoff = (uint32_t)(wm0 + (lane & 15)) * SRQ + ((lane >> 4) << 4);
#pragma unroll
    for (int kc = 0; kc < 4; kc++) {
        uint32_t qh[4], ql[4];
        ldsm_x4(qh, sb + AOFF_QHI + aoff + kc * 32);
        ldsm_x4(ql, sb + AOFF_QLO + aoff + kc * 32);
#pragma unroll
        for (int np = 0; np < 5; np++) {
            uint32_t bh[4], bl[4];
            uint32_t boff = (uint32_t)(wn * 80 + np * 16 + (lane & 15)) * SRQ
                          + ((lane >> 4) << 4) + kc * 32;
            ldsm_x4(bh, sb + AOFF_KHI + boff);
            ldsm_x4(bl, sb + AOFF_KLO + boff);
#pragma unroll
            for (int h2 = 0; h2 < 2; h2++) {
                const int nt = np * 2 + h2;
                mma_bf16(acc[nt], qh, bh[h2], bh[h2 + 2]);
                mma_bf16(acc[nt], qh, bl[h2], bl[h2 + 2]);
                mma_bf16(acc[nt], ql, bh[h2], bh[h2 + 2]);
            }
        }
    }

    const int lo_c = (t0 >= 128) ? g : 0;
    const int hi_c = (t0 >= 128) ? (127 + g) : (t0 + g);
    bool val0[10], val1[10];
    float vmax0 = NEGINF, vmax1 = NEGINF;
#pragma unroll
    for (int nt = 0; nt < 10; nt++) {
        int c0 = wn * 80 + nt * 8 + q * 2;
        int c1 = c0 + 1;
        val0[nt] = (c0 >= lo_c) && (c0 <= hi_c);
        val1[nt] = (c1 >= lo_c) && (c1 <= hi_c);
        if (val0[nt]) { vmax0 = fmaxf(vmax0, acc[nt][0]); vmax1 = fmaxf(vmax1, acc[nt][2]); }
        if (val1[nt]) { vmax0 = fmaxf(vmax0, acc[nt][1]); vmax1 = fmaxf(vmax1, acc[nt][3]); }
    }
    vmax0 = fmaxf(vmax0, __shfl_xor_sync(0xffffffffu, vmax0, 1));
    vmax0 = fmaxf(vmax0, __shfl_xor_sync(0xffffffffu, vmax0, 2));
    vmax1 = fmaxf(vmax1, __shfl_xor_sync(0xffffffffu, vmax1, 1));
    vmax1 = fmaxf(vmax1, __shfl_xor_sync(0xffffffffu, vmax1, 2));
    float* sM = (float*)(smem + AOFF_SM);
    if (q == 0) { sM[wn * 64 + wm0 + g] = vmax0; sM[wn * 64 + wm0 + g + 8] = vmax1; }
    __syncthreads();

    const float snk0 = sinks[kv * 8 + 2 * wm];
    const float snk1 = sinks[kv * 8 + 2 * wm + 1];
    const float m0 = fmaxf(fmaxf(sM[wm0 + g], sM[64 + wm0 + g]), snk0);
    const float m1 = fmaxf(fmaxf(sM[wm0 + g + 8], sM[64 + wm0 + g + 8]), snk1);
    float sum0 = 0.f, sum1 = 0.f;
#pragma unroll
    for (int nt = 0; nt < 10; nt++) {
        acc[nt][0] = val0[nt] ? __expf(acc[nt][0] - m0) : 0.f;
        acc[nt][1] = val1[nt] ? __expf(acc[nt][1] - m0) : 0.f;
        acc[nt][2] = val0[nt] ? __expf(acc[nt][2] - m1) : 0.f;
        acc[nt][3] = val1[nt] ? __expf(acc[nt][3] - m1) : 0.f;
        sum0 += acc[nt][0] + acc[nt][1];
        sum1 += acc[nt][2] + acc[nt][3];
    }
    sum0 += __shfl_xor_sync(0xffffffffu, sum0, 1);
    sum0 += __shfl_xor_sync(0xffffffffu, sum0, 2);
    sum1 += __shfl_xor_sync(0xffffffffu, sum1, 1);
    sum1 += __shfl_xor_sync(0xffffffffu, sum1, 2);
    float* sS = (float*)(smem + AOFF_SS);
    if (q == 0) { sS[wn * 64 + wm0 + g] = sum0; sS[wn * 64 + wm0 + g + 8] = sum1; }
    __syncthreads();

    float* sDen = (float*)(smem + AOFF_DEN);
    if (wn == 0 && q == 0) {
        int r0 = wm0 + g, r1 = r0 + 8;
        sDen[r0] = 1.f / (sS[r0] + sS[64 + r0] + __expf(snk0 - m0));
        sDen[r1] = 1.f / (sS[r1] + sS[64 + r1] + __expf(snk1 - m1));
    }

    float accO[8][4];
#pragma unroll
    for (int nt = 0; nt < 8; nt++)
#pragma unroll
        for (int e = 0; e < 4; e++) accO[nt][e] = 0.f;

#pragma unroll
    for (int kc = 0; kc < 5; kc++) {
        uint32_t ah[4], al[4];
        ah[0] = pack_split_b(acc[2 * kc][0],     acc[2 * kc][1],     &al[0]);
        ah[1] = pack_split_b(acc[2 * kc][2],     acc[2 * kc][3],     &al[1]);
        ah[2] = pack_split_b(acc[2 * kc + 1][0], acc[2 * kc + 1][1], &al[2]);
        ah[3] = pack_split_b(acc[2 * kc + 1][2], acc[2 * kc + 1][3], &al[3]);
#pragma unroll
        for (int np = 0; np < 4; np++) {
            uint32_t bh[4], bl[4];
            uint32_t boff = (uint32_t)(np * 16 + (lane & 15)) * SRVT
                          + ((lane >> 4) << 4) + wn * 160 + kc * 32;
            ldsm_x4(bh, sb + AOFF_VHI + boff);
            ldsm_x4(bl, sb + AOFF_VLO + boff);
#pragma unroll
            for (int h2 = 0; h2 < 2; h2++) {
                const int nt = np * 2 + h2;
                mma_bf16(accO[nt], ah, bh[h2], bh[h2 + 2]);
                mma_bf16(accO[nt], ah, bl[h2], bl[h2 + 2]);
                mma_bf16(accO[nt], al, bh[h2], bh[h2 + 2]);
            }
        }
    }

    float* sO = (float*)(smem + AOFF_O);
    if (wn == 0) {
#pragma unroll
        for (int nt = 0; nt < 8; nt++) {
            int c = nt * 8 + q * 2;
            *(float2*)&sO[(wm0 + g) * 68 + c]     = make_float2(accO[nt][0], accO[nt][1]);
            *(float2*)&sO[(wm0 + g + 8) * 68 + c] = make_float2(accO[nt][2], accO[nt][3]);
        }
    }
    __syncthreads();
    if (wn == 1) {
#pragma unroll
        for (int nt = 0; nt < 8; nt++) {
            int c = nt * 8 + q * 2;
            float2 a = *(float2*)&sO[(wm0 + g) * 68 + c];
            a.x += accO[nt][0]; a.y += accO[nt][1];
            *(float2*)&sO[(wm0 + g) * 68 + c] = a;
            float2 b = *(float2*)&sO[(wm0 + g + 8) * 68 + c];
            b.x += accO[nt][2]; b.y += accO[nt][3];
            *(float2*)&sO[(wm0 + g + 8) * 68 + c] = b;
        }
    }
    __syncthreads();

    // normalize + fp16 store (A operand of GEMM2)
    for (int idx = tid; idx < 4096; idx += 256) {
        int r = idx >> 6, d = idx & 63;
        float v = sO[r * 68 + d] * sDen[r];
        int i = t0 + (r & 7);
        int col = kv * 512 + (r >> 3) * 64 + d;
        oA[(size_t)i * Q_DIM + col] = __float2half_rn(v);
    }
}

// ---------------- launch ----------------
extern "C" void kernel_launch(void* const* d_in, const int* in_sizes, int n_in,
                              void* d_out, int out_size) {
    const float* x      = (const float*)d_in[0];
    const float* norm_w = (const float*)d_in[1];
    const float* qkv_w  = (const float*)d_in[2];
    const float* out_w  = (const float*)d_in[3];
    const float* sinks  = (const float*)d_in[4];
    float* out = (float*)d_out;

    float* QKV;
    __half *A, *B1, *B2;
    cudaGetSymbolAddress((void**)&QKV, g_QKV);
    cudaGetSymbolAddress((void**)&A,   g_A);
    cudaGetSymbolAddress((void**)&B1,  g_B1);
    cudaGetSymbolAddress((void**)&B2,  g_B2);

    cudaFuncSetAttribute(gemm_mma<false>, cudaFuncAttributeMaxDynamicSharedMemorySize, GEMM_SMEM);
    cudaFuncSetAttribute(gemm_mma<true>,  cudaFuncAttributeMaxDynamicSharedMemorySize, GEMM_SMEM);
    cudaFuncSetAttribute(attn_mma_kernel, cudaFuncAttributeMaxDynamicSharedMemorySize, ATTN_SMEM);

    // 1. RMSNorm -> fp16 A
    rmsnorm_f16_kernel<<<NTOK, 256>>>(x, norm_w, A);

    // 2. transpose qkv_w [2880][5120] -> B1 [5120][2880] fp16
    {
        dim3 grid(QKV_DIM / 32, HIDDEN / 32);
        trans_f16_kernel<<<grid, dim3(32, 8)>>>(qkv_w, B1, HIDDEN, QKV_DIM);
    }

    // 3. transpose out_w [4096][2880] -> B2 [2880][4096] fp16
    {
        dim3 grid(HIDDEN / 32, Q_DIM / 32);
        trans_f16_kernel<<<grid, dim3(32, 8)>>>(out_w, B2, Q_DIM, HIDDEN);
    }

    // 4. QKV GEMM (launch #4 -> ncu profiles this one)
    {
        dim3 grid(QKV_DIM / 128, NTOK / 64);
        gemm_mma<false><<<grid, 256, GEMM_SMEM>>>(A, B1, nullptr, QKV,
                                                  QKV_DIM, HIDDEN);
    }

    // 5. RoPE
    rope_kernel<<<NTOK, 256>>>(QKV);

    // 6. MMA attention (writes fp16 A for GEMM2)
    {
        dim3 grid(NTOK / 8, N_KV);
        attn_mma_kernel<<<grid, 256, ATTN_SMEM>>>(QKV, sinks, A);
    }

    // 7. out projection + residual
    {
        dim3 grid((HIDDEN + 127) / 128, NTOK / 64);
        gemm_mma<true><<<grid, 256, GEMM_SMEM>>>(A, B2, x, out,
                                                 HIDDEN, Q_DIM);
    }
}